// round 1
// baseline (speedup 1.0000x reference)
#include <cuda_runtime.h>

#define BB 8
#define C_ 256
#define HW_ 4096
#define CM_ 64
#define PHW_ 1024
#define EPS_ 1e-5f

// ---------------- scratch (static device memory, no allocation) ----------------
__device__ float d_gx[BB * PHW_ * C_];     // V: [b][m][c]   (pooled g conv)
__device__ float d_theta[BB * HW_ * CM_];  // Q: [b][n][c]
__device__ float d_phi[BB * PHW_ * CM_];   // K: [b][m][c]   (pooled phi conv)
__device__ float d_S[(size_t)BB * HW_ * PHW_]; // scores / probs
__device__ float d_y[BB * HW_ * C_];       // y: [b][n][c]

// ======================================================================
// Kernel 1: 1x1 conv over full-res tile (2 image rows = 128 pixels) for a
// 64-out-channel tile, then fused 2x2 maxpool + bias.
// out[b][m][oc_total] layout, m = pooled pixel.
// grid: (cout_total/64, 32 /*ph*/, B), block 256
// ======================================================================
union SMemConv {
    struct { float Xs[32][128]; float Ws[64][33]; } in;
    float Res[128][65];
};

__global__ __launch_bounds__(256) void conv_pool_kernel(
    const float* __restrict__ x, const float* __restrict__ w,
    const float* __restrict__ bias, float* __restrict__ out,
    int cin_off, int cin, int cout_total)
{
    __shared__ SMemConv sm;
    const int b = blockIdx.z, ph = blockIdx.y, o0 = blockIdx.x * 64;
    const int tid = threadIdx.x;
    const int ocg = tid & 7, pxg = tid >> 3;
    const float* xb = x + ((size_t)b * C_ + cin_off) * HW_ + ph * 128;

    float acc[4][8];
#pragma unroll
    for (int i = 0; i < 4; i++)
#pragma unroll
        for (int j = 0; j < 8; j++) acc[i][j] = 0.f;

    for (int kc = 0; kc < cin; kc += 32) {
#pragma unroll
        for (int t = 0; t < 16; t++) {
            int e = tid + t * 256;
            int c = e >> 7, p = e & 127;
            sm.in.Xs[c][p] = xb[(size_t)(kc + c) * HW_ + p];
        }
#pragma unroll
        for (int t = 0; t < 8; t++) {
            int e = tid + t * 256;
            int o = e >> 5, c = e & 31;
            sm.in.Ws[o][c] = w[(size_t)(o0 + o) * cin + kc + c];
        }
        __syncthreads();
#pragma unroll
        for (int k = 0; k < 32; k++) {
            float xv[4], wv[8];
#pragma unroll
            for (int i = 0; i < 4; i++) xv[i] = sm.in.Xs[k][pxg + 32 * i];
#pragma unroll
            for (int j = 0; j < 8; j++) wv[j] = sm.in.Ws[ocg + 8 * j][k];
#pragma unroll
            for (int i = 0; i < 4; i++)
#pragma unroll
                for (int j = 0; j < 8; j++) acc[i][j] += xv[i] * wv[j];
        }
        __syncthreads();
    }
#pragma unroll
    for (int i = 0; i < 4; i++)
#pragma unroll
        for (int j = 0; j < 8; j++) sm.Res[pxg + 32 * i][ocg + 8 * j] = acc[i][j];
    __syncthreads();
    // pool 2x2 + bias, write [b][m][cout_total]
#pragma unroll
    for (int t = 0; t < 8; t++) {
        int e = tid + t * 256;
        int pw = e >> 6, o = e & 63;
        float v = fmaxf(fmaxf(sm.Res[2 * pw][o], sm.Res[2 * pw + 1][o]),
                        fmaxf(sm.Res[64 + 2 * pw][o], sm.Res[65 + 2 * pw][o]));
        out[((size_t)b * PHW_ + ph * 32 + pw) * cout_total + o0 + o] = v + bias[o0 + o];
    }
}

// ======================================================================
// Kernel 2: theta conv (cin=64, cout=64, no pool), Q[b][n][64]
// grid: (32 /*pixel tiles*/, B), block 256
// ======================================================================
__global__ __launch_bounds__(256) void conv_theta_kernel(
    const float* __restrict__ x, const float* __restrict__ w,
    const float* __restrict__ bias, float* __restrict__ out)
{
    __shared__ SMemConv sm;
    const int b = blockIdx.y, pt = blockIdx.x;
    const int tid = threadIdx.x;
    const int ocg = tid & 7, pxg = tid >> 3;
    const float* xb = x + (size_t)b * C_ * HW_ + pt * 128;

    float acc[4][8];
#pragma unroll
    for (int i = 0; i < 4; i++)
#pragma unroll
        for (int j = 0; j < 8; j++) acc[i][j] = 0.f;

    for (int kc = 0; kc < 64; kc += 32) {
#pragma unroll
        for (int t = 0; t < 16; t++) {
            int e = tid + t * 256;
            int c = e >> 7, p = e & 127;
            sm.in.Xs[c][p] = xb[(size_t)(kc + c) * HW_ + p];
        }
#pragma unroll
        for (int t = 0; t < 8; t++) {
            int e = tid + t * 256;
            int o = e >> 5, c = e & 31;
            sm.in.Ws[o][c] = w[(size_t)o * 64 + kc + c];
        }
        __syncthreads();
#pragma unroll
        for (int k = 0; k < 32; k++) {
            float xv[4], wv[8];
#pragma unroll
            for (int i = 0; i < 4; i++) xv[i] = sm.in.Xs[k][pxg + 32 * i];
#pragma unroll
            for (int j = 0; j < 8; j++) wv[j] = sm.in.Ws[ocg + 8 * j][k];
#pragma unroll
            for (int i = 0; i < 4; i++)
#pragma unroll
                for (int j = 0; j < 8; j++) acc[i][j] += xv[i] * wv[j];
        }
        __syncthreads();
    }
#pragma unroll
    for (int i = 0; i < 4; i++)
#pragma unroll
        for (int j = 0; j < 8; j++) sm.Res[pxg + 32 * i][ocg + 8 * j] = acc[i][j];
    __syncthreads();
#pragma unroll
    for (int t = 0; t < 32; t++) {
        int e = tid + t * 256;
        int p = e >> 6, o = e & 63;
        out[((size_t)b * HW_ + pt * 128 + p) * 64 + o] = sm.Res[p][o] + bias[o];
    }
}

// ======================================================================
// Kernel 3: S = Q @ K^T.  Q[b][4096][64], K[b][1024][64] -> S[b][4096][1024]
// tile: 128 n-rows x 64 m-cols, Kdim 64. grid (16, 32, B), block 256
// ======================================================================
union SMemQK {
    struct { float As[32][129]; float Bs[64][33]; } in;
    float Res[128][65];
};

__global__ __launch_bounds__(256) void qk_kernel(
    const float* __restrict__ Q, const float* __restrict__ K, float* __restrict__ S)
{
    __shared__ SMemQK sm;
    const int b = blockIdx.z, nt = blockIdx.y, mt = blockIdx.x;
    const int tid = threadIdx.x;
    const int ocg = tid & 7, pxg = tid >> 3;
    const float* Qb = Q + ((size_t)b * HW_ + nt * 128) * 64;
    const float* Kb = K + ((size_t)b * PHW_ + mt * 64) * 64;

    float acc[4][8];
#pragma unroll
    for (int i = 0; i < 4; i++)
#pragma unroll
        for (int j = 0; j < 8; j++) acc[i][j] = 0.f;

    for (int kc = 0; kc < 64; kc += 32) {
#pragma unroll
        for (int t = 0; t < 16; t++) {
            int e = tid + t * 256;
            int p = e >> 5, k = e & 31;
            sm.in.As[k][p] = Qb[(size_t)p * 64 + kc + k];
        }
#pragma unroll
        for (int t = 0; t < 8; t++) {
            int e = tid + t * 256;
            int m = e >> 5, k = e & 31;
            sm.in.Bs[m][k] = Kb[(size_t)m * 64 + kc + k];
        }
        __syncthreads();
#pragma unroll
        for (int k = 0; k < 32; k++) {
            float xv[4], wv[8];
#pragma unroll
            for (int i = 0; i < 4; i++) xv[i] = sm.in.As[k][pxg + 32 * i];
#pragma unroll
            for (int j = 0; j < 8; j++) wv[j] = sm.in.Bs[ocg + 8 * j][k];
#pragma unroll
            for (int i = 0; i < 4; i++)
#pragma unroll
                for (int j = 0; j < 8; j++) acc[i][j] += xv[i] * wv[j];
        }
        __syncthreads();
    }
#pragma unroll
    for (int i = 0; i < 4; i++)
#pragma unroll
        for (int j = 0; j < 8; j++) sm.Res[pxg + 32 * i][ocg + 8 * j] = acc[i][j];
    __syncthreads();
#pragma unroll
    for (int t = 0; t < 32; t++) {
        int e = tid + t * 256;
        int p = e >> 6, m = e & 63;
        S[((size_t)b * HW_ + nt * 128 + p) * PHW_ + mt * 64 + m] = sm.Res[p][m];
    }
}

// ======================================================================
// Kernel 4: row softmax over 1024 cols. grid 32768, block 256.
// ======================================================================
__global__ __launch_bounds__(256) void softmax_kernel(float* __restrict__ S)
{
    const size_t r = blockIdx.x;
    float* row = S + r * PHW_;
    const int tid = threadIdx.x;
    const int wid = tid >> 5, lid = tid & 31;
    __shared__ float redm[8], reds[8];

    float4 v = reinterpret_cast<float4*>(row)[tid];
    float m = fmaxf(fmaxf(v.x, v.y), fmaxf(v.z, v.w));
#pragma unroll
    for (int o = 16; o; o >>= 1) m = fmaxf(m, __shfl_xor_sync(0xffffffffu, m, o));
    if (lid == 0) redm[wid] = m;
    __syncthreads();
    float bm = redm[0];
#pragma unroll
    for (int i = 1; i < 8; i++) bm = fmaxf(bm, redm[i]);

    v.x = __expf(v.x - bm); v.y = __expf(v.y - bm);
    v.z = __expf(v.z - bm); v.w = __expf(v.w - bm);
    float s = v.x + v.y + v.z + v.w;
#pragma unroll
    for (int o = 16; o; o >>= 1) s += __shfl_xor_sync(0xffffffffu, s, o);
    if (lid == 0) reds[wid] = s;
    __syncthreads();
    float tot = reds[0];
#pragma unroll
    for (int i = 1; i < 8; i++) tot += reds[i];
    float inv = 1.f / tot;
    v.x *= inv; v.y *= inv; v.z *= inv; v.w *= inv;
    reinterpret_cast<float4*>(row)[tid] = v;
}

// ======================================================================
// Kernel 5: Y = P @ V.  P[b][4096][1024], V[b][1024][256] -> Y[b][4096][256]
// tile 128 x 64, Kdim 1024. grid (4, 32, B), block 256
// ======================================================================
union SMemPV {
    struct { float Ps[32][129]; float Vs[32][64]; } in;
    float Res[128][65];
};

__global__ __launch_bounds__(256) void pv_kernel(
    const float* __restrict__ P, const float* __restrict__ V, float* __restrict__ Y)
{
    __shared__ SMemPV sm;
    const int b = blockIdx.z, nt = blockIdx.y, ct = blockIdx.x;
    const int tid = threadIdx.x;
    const int ocg = tid & 7, pxg = tid >> 3;
    const float* Pb = P + ((size_t)b * HW_ + nt * 128) * PHW_;
    const float* Vb = V + (size_t)b * PHW_ * C_ + ct * 64;

    float acc[4][8];
#pragma unroll
    for (int i = 0; i < 4; i++)
#pragma unroll
        for (int j = 0; j < 8; j++) acc[i][j] = 0.f;

    for (int kc = 0; kc < PHW_; kc += 32) {
#pragma unroll
        for (int t = 0; t < 16; t++) {
            int e = tid + t * 256;
            int p = e >> 5, k = e & 31;
            sm.in.Ps[k][p] = Pb[(size_t)p * PHW_ + kc + k];
        }
#pragma unroll
        for (int t = 0; t < 8; t++) {
            int e = tid + t * 256;
            int k = e >> 6, o = e & 63;
            sm.in.Vs[k][o] = Vb[(size_t)(kc + k) * C_ + o];
        }
        __syncthreads();
#pragma unroll
        for (int k = 0; k < 32; k++) {
            float xv[4], wv[8];
#pragma unroll
            for (int i = 0; i < 4; i++) xv[i] = sm.in.Ps[k][pxg + 32 * i];
#pragma unroll
            for (int j = 0; j < 8; j++) wv[j] = sm.in.Vs[k][ocg + 8 * j];
#pragma unroll
            for (int i = 0; i < 4; i++)
#pragma unroll
                for (int j = 0; j < 8; j++) acc[i][j] += xv[i] * wv[j];
        }
        __syncthreads();
    }
#pragma unroll
    for (int i = 0; i < 4; i++)
#pragma unroll
        for (int j = 0; j < 8; j++) sm.Res[pxg + 32 * i][ocg + 8 * j] = acc[i][j];
    __syncthreads();
#pragma unroll
    for (int t = 0; t < 32; t++) {
        int e = tid + t * 256;
        int p = e >> 6, o = e & 63;
        Y[((size_t)b * HW_ + nt * 128 + p) * C_ + ct * 64 + o] = sm.Res[p][o];
    }
}

// ======================================================================
// Kernel 6: out = BN(Y @ W^T + Wb) + x.  Y[b][n][256] -> out[b][c][n]
// tile 128 px x 64 oc, Kdim 256. grid (4, 32, B), block 256
// ======================================================================
__global__ __launch_bounds__(256) void final_kernel(
    const float* __restrict__ Y, const float* __restrict__ Ww, const float* __restrict__ Wb,
    const float* __restrict__ gamma, const float* __restrict__ beta,
    const float* __restrict__ mean, const float* __restrict__ var,
    const float* __restrict__ x, float* __restrict__ out)
{
    __shared__ SMemQK sm;
    const int b = blockIdx.z, nt = blockIdx.y, o0 = blockIdx.x * 64;
    const int tid = threadIdx.x;
    const int ocg = tid & 7, pxg = tid >> 3;
    const float* Yb = Y + ((size_t)b * HW_ + nt * 128) * C_;

    float acc[4][8];
#pragma unroll
    for (int i = 0; i < 4; i++)
#pragma unroll
        for (int j = 0; j < 8; j++) acc[i][j] = 0.f;

    for (int kc = 0; kc < C_; kc += 32) {
#pragma unroll
        for (int t = 0; t < 16; t++) {
            int e = tid + t * 256;
            int p = e >> 5, k = e & 31;
            sm.in.As[k][p] = Yb[(size_t)p * C_ + kc + k];
        }
#pragma unroll
        for (int t = 0; t < 8; t++) {
            int e = tid + t * 256;
            int o = e >> 5, k = e & 31;
            sm.in.Bs[o][k] = Ww[(size_t)(o0 + o) * C_ + kc + k];
        }
        __syncthreads();
#pragma unroll
        for (int k = 0; k < 32; k++) {
            float xv[4], wv[8];
#pragma unroll
            for (int i = 0; i < 4; i++) xv[i] = sm.in.As[k][pxg + 32 * i];
#pragma unroll
            for (int j = 0; j < 8; j++) wv[j] = sm.in.Bs[ocg + 8 * j][k];
#pragma unroll
            for (int i = 0; i < 4; i++)
#pragma unroll
                for (int j = 0; j < 8; j++) acc[i][j] += xv[i] * wv[j];
        }
        __syncthreads();
    }
#pragma unroll
    for (int i = 0; i < 4; i++)
#pragma unroll
        for (int j = 0; j < 8; j++) sm.Res[pxg + 32 * i][ocg + 8 * j] = acc[i][j];
    __syncthreads();
    // BN + residual, write channel-major out[b][c][n]
#pragma unroll
    for (int t = 0; t < 32; t++) {
        int e = tid + t * 256;
        int o = e >> 7, p = e & 127;
        int oc = o0 + o;
        float scale = gamma[oc] * rsqrtf(var[oc] + EPS_);
        size_t gidx = ((size_t)b * C_ + oc) * HW_ + nt * 128 + p;
        float v = (sm.Res[p][o] + Wb[oc] - mean[oc]) * scale + beta[oc] + x[gidx];
        out[gidx] = v;
    }
}

// ======================================================================
extern "C" void kernel_launch(void* const* d_in, const int* in_sizes, int n_in,
                              void* d_out, int out_size)
{
    const float* x       = (const float*)d_in[0];
    const float* g_w     = (const float*)d_in[1];
    const float* g_b     = (const float*)d_in[2];
    const float* theta_w = (const float*)d_in[3];
    const float* theta_b = (const float*)d_in[4];
    const float* phi_w   = (const float*)d_in[5];
    const float* phi_b   = (const float*)d_in[6];
    const float* W_w     = (const float*)d_in[7];
    const float* W_b     = (const float*)d_in[8];
    const float* bn_g    = (const float*)d_in[9];
    const float* bn_b    = (const float*)d_in[10];
    const float* bn_m    = (const float*)d_in[11];
    const float* bn_v    = (const float*)d_in[12];
    float* out = (float*)d_out;

    float *gx, *th, *ph, *S, *y;
    cudaGetSymbolAddress((void**)&gx, d_gx);
    cudaGetSymbolAddress((void**)&th, d_theta);
    cudaGetSymbolAddress((void**)&ph, d_phi);
    cudaGetSymbolAddress((void**)&S,  d_S);
    cudaGetSymbolAddress((void**)&y,  d_y);

    // 1. g conv + pool -> V
    conv_pool_kernel<<<dim3(4, 32, BB), 256>>>(x, g_w, g_b, gx, 0, 256, 256);
    // 2. phi conv + pool -> K
    conv_pool_kernel<<<dim3(1, 32, BB), 256>>>(x, phi_w, phi_b, ph, 64, 192, 64);
    // 3. theta conv -> Q
    conv_theta_kernel<<<dim3(32, BB), 256>>>(x, theta_w, theta_b, th);
    // 4. S = Q K^T
    qk_kernel<<<dim3(16, 32, BB), 256>>>(th, ph, S);
    // 5. softmax
    softmax_kernel<<<dim3(BB * HW_), 256>>>(S);
    // 6. Y = P V
    pv_kernel<<<dim3(4, 32, BB), 256>>>(S, gx, y);
    // 7. final conv + BN + residual
    final_kernel<<<dim3(4, 32, BB), 256>>>(y, W_w, W_b, bn_g, bn_b, bn_m, bn_v, x, out);
}

// round 2
// speedup vs baseline: 1.0051x; 1.0051x over previous
#include <cuda_runtime.h>

#define BB 8
#define C_ 256
#define HW_ 4096
#define CM_ 64
#define PHW_ 1024
#define EPS_ 1e-5f

// ---------------- scratch (static device memory, no allocation) ----------------
__device__ float d_gx[BB * PHW_ * C_];     // V: [b][m][c]   (pooled g conv)
__device__ float d_theta[BB * HW_ * CM_];  // Q: [b][n][c]
__device__ float d_phi[BB * PHW_ * CM_];   // K: [b][m][c]   (pooled phi conv)
__device__ float d_S[(size_t)BB * HW_ * PHW_]; // scores / probs
__device__ float d_y[BB * HW_ * C_];       // y: [b][n][c]

// ======================================================================
// Kernel 1: 1x1 conv over full-res tile (2 image rows = 128 pixels) for a
// 64-out-channel tile, then fused 2x2 maxpool + bias.
// out[b][m][oc_total] layout, m = pooled pixel.
// grid: (cout_total/64, 32 /*ph*/, B), block 256
// ======================================================================
union SMemConv {
    struct { float Xs[32][128]; float Ws[64][33]; } in;
    float Res[128][65];
};

__global__ __launch_bounds__(256) void conv_pool_kernel(
    const float* __restrict__ x, const float* __restrict__ w,
    const float* __restrict__ bias, float* __restrict__ out,
    int cin_off, int cin, int cout_total)
{
    __shared__ SMemConv sm;
    const int b = blockIdx.z, ph = blockIdx.y, o0 = blockIdx.x * 64;
    const int tid = threadIdx.x;
    const int ocg = tid & 7, pxg = tid >> 3;
    const float* xb = x + ((size_t)b * C_ + cin_off) * HW_ + ph * 128;

    float acc[4][8];
#pragma unroll
    for (int i = 0; i < 4; i++)
#pragma unroll
        for (int j = 0; j < 8; j++) acc[i][j] = 0.f;

    for (int kc = 0; kc < cin; kc += 32) {
#pragma unroll
        for (int t = 0; t < 16; t++) {
            int e = tid + t * 256;
            int c = e >> 7, p = e & 127;
            sm.in.Xs[c][p] = xb[(size_t)(kc + c) * HW_ + p];
        }
#pragma unroll
        for (int t = 0; t < 8; t++) {
            int e = tid + t * 256;
            int o = e >> 5, c = e & 31;
            sm.in.Ws[o][c] = w[(size_t)(o0 + o) * cin + kc + c];
        }
        __syncthreads();
#pragma unroll
        for (int k = 0; k < 32; k++) {
            float xv[4], wv[8];
#pragma unroll
            for (int i = 0; i < 4; i++) xv[i] = sm.in.Xs[k][pxg + 32 * i];
#pragma unroll
            for (int j = 0; j < 8; j++) wv[j] = sm.in.Ws[ocg + 8 * j][k];
#pragma unroll
            for (int i = 0; i < 4; i++)
#pragma unroll
                for (int j = 0; j < 8; j++) acc[i][j] += xv[i] * wv[j];
        }
        __syncthreads();
    }
#pragma unroll
    for (int i = 0; i < 4; i++)
#pragma unroll
        for (int j = 0; j < 8; j++) sm.Res[pxg + 32 * i][ocg + 8 * j] = acc[i][j];
    __syncthreads();
    // pool 2x2 + bias, write [b][m][cout_total]
#pragma unroll
    for (int t = 0; t < 8; t++) {
        int e = tid + t * 256;
        int pw = e >> 6, o = e & 63;
        float v = fmaxf(fmaxf(sm.Res[2 * pw][o], sm.Res[2 * pw + 1][o]),
                        fmaxf(sm.Res[64 + 2 * pw][o], sm.Res[65 + 2 * pw][o]));
        out[((size_t)b * PHW_ + ph * 32 + pw) * cout_total + o0 + o] = v + bias[o0 + o];
    }
}

// ======================================================================
// Kernel 2: theta conv (cin=64, cout=64, no pool), Q[b][n][64]
// grid: (32 /*pixel tiles*/, B), block 256
// ======================================================================
__global__ __launch_bounds__(256) void conv_theta_kernel(
    const float* __restrict__ x, const float* __restrict__ w,
    const float* __restrict__ bias, float* __restrict__ out)
{
    __shared__ SMemConv sm;
    const int b = blockIdx.y, pt = blockIdx.x;
    const int tid = threadIdx.x;
    const int ocg = tid & 7, pxg = tid >> 3;
    const float* xb = x + (size_t)b * C_ * HW_ + pt * 128;

    float acc[4][8];
#pragma unroll
    for (int i = 0; i < 4; i++)
#pragma unroll
        for (int j = 0; j < 8; j++) acc[i][j] = 0.f;

    for (int kc = 0; kc < 64; kc += 32) {
#pragma unroll
        for (int t = 0; t < 16; t++) {
            int e = tid + t * 256;
            int c = e >> 7, p = e & 127;
            sm.in.Xs[c][p] = xb[(size_t)(kc + c) * HW_ + p];
        }
#pragma unroll
        for (int t = 0; t < 8; t++) {
            int e = tid + t * 256;
            int o = e >> 5, c = e & 31;
            sm.in.Ws[o][c] = w[(size_t)o * 64 + kc + c];
        }
        __syncthreads();
#pragma unroll
        for (int k = 0; k < 32; k++) {
            float xv[4], wv[8];
#pragma unroll
            for (int i = 0; i < 4; i++) xv[i] = sm.in.Xs[k][pxg + 32 * i];
#pragma unroll
            for (int j = 0; j < 8; j++) wv[j] = sm.in.Ws[ocg + 8 * j][k];
#pragma unroll
            for (int i = 0; i < 4; i++)
#pragma unroll
                for (int j = 0; j < 8; j++) acc[i][j] += xv[i] * wv[j];
        }
        __syncthreads();
    }
#pragma unroll
    for (int i = 0; i < 4; i++)
#pragma unroll
        for (int j = 0; j < 8; j++) sm.Res[pxg + 32 * i][ocg + 8 * j] = acc[i][j];
    __syncthreads();
#pragma unroll
    for (int t = 0; t < 32; t++) {
        int e = tid + t * 256;
        int p = e >> 6, o = e & 63;
        out[((size_t)b * HW_ + pt * 128 + p) * 64 + o] = sm.Res[p][o] + bias[o];
    }
}

// ======================================================================
// Kernel 3: S = Q @ K^T.  Q[b][4096][64], K[b][1024][64] -> S[b][4096][1024]
// tile: 128 n-rows x 64 m-cols, Kdim 64. grid (16, 32, B), block 256
// ======================================================================
union SMemQK {
    struct { float As[32][129]; float Bs[64][33]; } in;
    float Res[128][65];
};

__global__ __launch_bounds__(256) void qk_kernel(
    const float* __restrict__ Q, const float* __restrict__ K, float* __restrict__ S)
{
    __shared__ SMemQK sm;
    const int b = blockIdx.z, nt = blockIdx.y, mt = blockIdx.x;
    const int tid = threadIdx.x;
    const int ocg = tid & 7, pxg = tid >> 3;
    const float* Qb = Q + ((size_t)b * HW_ + nt * 128) * 64;
    const float* Kb = K + ((size_t)b * PHW_ + mt * 64) * 64;

    float acc[4][8];
#pragma unroll
    for (int i = 0; i < 4; i++)
#pragma unroll
        for (int j = 0; j < 8; j++) acc[i][j] = 0.f;

    for (int kc = 0; kc < 64; kc += 32) {
#pragma unroll
        for (int t = 0; t < 16; t++) {
            int e = tid + t * 256;
            int p = e >> 5, k = e & 31;
            sm.in.As[k][p] = Qb[(size_t)p * 64 + kc + k];
        }
#pragma unroll
        for (int t = 0; t < 8; t++) {
            int e = tid + t * 256;
            int m = e >> 5, k = e & 31;
            sm.in.Bs[m][k] = Kb[(size_t)m * 64 + kc + k];
        }
        __syncthreads();
#pragma unroll
        for (int k = 0; k < 32; k++) {
            float xv[4], wv[8];
#pragma unroll
            for (int i = 0; i < 4; i++) xv[i] = sm.in.As[k][pxg + 32 * i];
#pragma unroll
            for (int j = 0; j < 8; j++) wv[j] = sm.in.Bs[ocg + 8 * j][k];
#pragma unroll
            for (int i = 0; i < 4; i++)
#pragma unroll
                for (int j = 0; j < 8; j++) acc[i][j] += xv[i] * wv[j];
        }
        __syncthreads();
    }
#pragma unroll
    for (int i = 0; i < 4; i++)
#pragma unroll
        for (int j = 0; j < 8; j++) sm.Res[pxg + 32 * i][ocg + 8 * j] = acc[i][j];
    __syncthreads();
#pragma unroll
    for (int t = 0; t < 32; t++) {
        int e = tid + t * 256;
        int p = e >> 6, m = e & 63;
        S[((size_t)b * HW_ + nt * 128 + p) * PHW_ + mt * 64 + m] = sm.Res[p][m];
    }
}

// ======================================================================
// Kernel 4: row softmax over 1024 cols. grid 32768, block 256.
// ======================================================================
__global__ __launch_bounds__(256) void softmax_kernel(float* __restrict__ S)
{
    const size_t r = blockIdx.x;
    float* row = S + r * PHW_;
    const int tid = threadIdx.x;
    const int wid = tid >> 5, lid = tid & 31;
    __shared__ float redm[8], reds[8];

    float4 v = reinterpret_cast<float4*>(row)[tid];
    float m = fmaxf(fmaxf(v.x, v.y), fmaxf(v.z, v.w));
#pragma unroll
    for (int o = 16; o; o >>= 1) m = fmaxf(m, __shfl_xor_sync(0xffffffffu, m, o));
    if (lid == 0) redm[wid] = m;
    __syncthreads();
    float bm = redm[0];
#pragma unroll
    for (int i = 1; i < 8; i++) bm = fmaxf(bm, redm[i]);

    v.x = __expf(v.x - bm); v.y = __expf(v.y - bm);
    v.z = __expf(v.z - bm); v.w = __expf(v.w - bm);
    float s = v.x + v.y + v.z + v.w;
#pragma unroll
    for (int o = 16; o; o >>= 1) s += __shfl_xor_sync(0xffffffffu, s, o);
    if (lid == 0) reds[wid] = s;
    __syncthreads();
    float tot = reds[0];
#pragma unroll
    for (int i = 1; i < 8; i++) tot += reds[i];
    float inv = 1.f / tot;
    v.x *= inv; v.y *= inv; v.z *= inv; v.w *= inv;
    reinterpret_cast<float4*>(row)[tid] = v;
}

// ======================================================================
// Kernel 5: Y = P @ V.  P[b][4096][1024], V[b][1024][256] -> Y[b][4096][256]
// tile 128 x 64, Kdim 1024. grid (4, 32, B), block 256
// ======================================================================
union SMemPV {
    struct { float Ps[32][129]; float Vs[32][64]; } in;
    float Res[128][65];
};

__global__ __launch_bounds__(256) void pv_kernel(
    const float* __restrict__ P, const float* __restrict__ V, float* __restrict__ Y)
{
    __shared__ SMemPV sm;
    const int b = blockIdx.z, nt = blockIdx.y, ct = blockIdx.x;
    const int tid = threadIdx.x;
    const int ocg = tid & 7, pxg = tid >> 3;
    const float* Pb = P + ((size_t)b * HW_ + nt * 128) * PHW_;
    const float* Vb = V + (size_t)b * PHW_ * C_ + ct * 64;

    float acc[4][8];
#pragma unroll
    for (int i = 0; i < 4; i++)
#pragma unroll
        for (int j = 0; j < 8; j++) acc[i][j] = 0.f;

    for (int kc = 0; kc < PHW_; kc += 32) {
#pragma unroll
        for (int t = 0; t < 16; t++) {
            int e = tid + t * 256;
            int p = e >> 5, k = e & 31;
            sm.in.Ps[k][p] = Pb[(size_t)p * PHW_ + kc + k];
        }
#pragma unroll
        for (int t = 0; t < 8; t++) {
            int e = tid + t * 256;
            int k = e >> 6, o = e & 63;
            sm.in.Vs[k][o] = Vb[(size_t)(kc + k) * C_ + o];
        }
        __syncthreads();
#pragma unroll
        for (int k = 0; k < 32; k++) {
            float xv[4], wv[8];
#pragma unroll
            for (int i = 0; i < 4; i++) xv[i] = sm.in.Ps[k][pxg + 32 * i];
#pragma unroll
            for (int j = 0; j < 8; j++) wv[j] = sm.in.Vs[k][ocg + 8 * j];
#pragma unroll
            for (int i = 0; i < 4; i++)
#pragma unroll
                for (int j = 0; j < 8; j++) acc[i][j] += xv[i] * wv[j];
        }
        __syncthreads();
    }
#pragma unroll
    for (int i = 0; i < 4; i++)
#pragma unroll
        for (int j = 0; j < 8; j++) sm.Res[pxg + 32 * i][ocg + 8 * j] = acc[i][j];
    __syncthreads();
#pragma unroll
    for (int t = 0; t < 32; t++) {
        int e = tid + t * 256;
        int p = e >> 6, o = e & 63;
        Y[((size_t)b * HW_ + nt * 128 + p) * C_ + ct * 64 + o] = sm.Res[p][o];
    }
}

// ======================================================================
// Kernel 6: out = BN(Y @ W^T + Wb) + x.  Y[b][n][256] -> out[b][c][n]
// tile 128 px x 64 oc, Kdim 256. grid (4, 32, B), block 256
// ======================================================================
__global__ __launch_bounds__(256) void final_kernel(
    const float* __restrict__ Y, const float* __restrict__ Ww, const float* __restrict__ Wb,
    const float* __restrict__ gamma, const float* __restrict__ beta,
    const float* __restrict__ mean, const float* __restrict__ var,
    const float* __restrict__ x, float* __restrict__ out)
{
    __shared__ SMemQK sm;
    const int b = blockIdx.z, nt = blockIdx.y, o0 = blockIdx.x * 64;
    const int tid = threadIdx.x;
    const int ocg = tid & 7, pxg = tid >> 3;
    const float* Yb = Y + ((size_t)b * HW_ + nt * 128) * C_;

    float acc[4][8];
#pragma unroll
    for (int i = 0; i < 4; i++)
#pragma unroll
        for (int j = 0; j < 8; j++) acc[i][j] = 0.f;

    for (int kc = 0; kc < C_; kc += 32) {
#pragma unroll
        for (int t = 0; t < 16; t++) {
            int e = tid + t * 256;
            int p = e >> 5, k = e & 31;
            sm.in.As[k][p] = Yb[(size_t)p * C_ + kc + k];
        }
#pragma unroll
        for (int t = 0; t < 8; t++) {
            int e = tid + t * 256;
            int o = e >> 5, k = e & 31;
            sm.in.Bs[o][k] = Ww[(size_t)(o0 + o) * C_ + kc + k];
        }
        __syncthreads();
#pragma unroll
        for (int k = 0; k < 32; k++) {
            float xv[4], wv[8];
#pragma unroll
            for (int i = 0; i < 4; i++) xv[i] = sm.in.As[k][pxg + 32 * i];
#pragma unroll
            for (int j = 0; j < 8; j++) wv[j] = sm.in.Bs[ocg + 8 * j][k];
#pragma unroll
            for (int i = 0; i < 4; i++)
#pragma unroll
                for (int j = 0; j < 8; j++) acc[i][j] += xv[i] * wv[j];
        }
        __syncthreads();
    }
#pragma unroll
    for (int i = 0; i < 4; i++)
#pragma unroll
        for (int j = 0; j < 8; j++) sm.Res[pxg + 32 * i][ocg + 8 * j] = acc[i][j];
    __syncthreads();
    // BN + residual, write channel-major out[b][c][n]
#pragma unroll
    for (int t = 0; t < 32; t++) {
        int e = tid + t * 256;
        int o = e >> 7, p = e & 127;
        int oc = o0 + o;
        float scale = gamma[oc] * rsqrtf(var[oc] + EPS_);
        size_t gidx = ((size_t)b * C_ + oc) * HW_ + nt * 128 + p;
        float v = (sm.Res[p][o] + Wb[oc] - mean[oc]) * scale + beta[oc] + x[gidx];
        out[gidx] = v;
    }
}

// ======================================================================
extern "C" void kernel_launch(void* const* d_in, const int* in_sizes, int n_in,
                              void* d_out, int out_size)
{
    const float* x       = (const float*)d_in[0];
    const float* g_w     = (const float*)d_in[1];
    const float* g_b     = (const float*)d_in[2];
    const float* theta_w = (const float*)d_in[3];
    const float* theta_b = (const float*)d_in[4];
    const float* phi_w   = (const float*)d_in[5];
    const float* phi_b   = (const float*)d_in[6];
    const float* W_w     = (const float*)d_in[7];
    const float* W_b     = (const float*)d_in[8];
    const float* bn_g    = (const float*)d_in[9];
    const float* bn_b    = (const float*)d_in[10];
    const float* bn_m    = (const float*)d_in[11];
    const float* bn_v    = (const float*)d_in[12];
    float* out = (float*)d_out;

    float *gx, *th, *ph, *S, *y;
    cudaGetSymbolAddress((void**)&gx, d_gx);
    cudaGetSymbolAddress((void**)&th, d_theta);
    cudaGetSymbolAddress((void**)&ph, d_phi);
    cudaGetSymbolAddress((void**)&S,  d_S);
    cudaGetSymbolAddress((void**)&y,  d_y);

    // 1. g conv + pool -> V
    conv_pool_kernel<<<dim3(4, 32, BB), 256>>>(x, g_w, g_b, gx, 0, 256, 256);
    // 2. phi conv + pool -> K
    conv_pool_kernel<<<dim3(1, 32, BB), 256>>>(x, phi_w, phi_b, ph, 64, 192, 64);
    // 3. theta conv -> Q
    conv_theta_kernel<<<dim3(32, BB), 256>>>(x, theta_w, theta_b, th);
    // 4. S = Q K^T
    qk_kernel<<<dim3(16, 32, BB), 256>>>(th, ph, S);
    // 5. softmax
    softmax_kernel<<<dim3(BB * HW_), 256>>>(S);
    // 6. Y = P V
    pv_kernel<<<dim3(4, 32, BB), 256>>>(S, gx, y);
    // 7. final conv + BN + residual
    final_kernel<<<dim3(4, 32, BB), 256>>>(y, W_w, W_b, bn_g, bn_b, bn_m, bn_v, x, out);
}

// round 5
// speedup vs baseline: 1.6455x; 1.6371x over previous
#include <cuda_runtime.h>
#include <cuda_bf16.h>
#include <cstdint>

#define BB 8
#define C_ 256
#define HW_ 4096
#define PHW_ 1024
#define EPS_ 1e-5f

// ---------------- mma.sync helpers (sm_80+ path, valid on sm_103 base) ----
__device__ __forceinline__ uint32_t smem_to_u32(const void* p) {
    uint32_t a;
    asm("{ .reg .u64 t; cvta.to.shared.u64 t, %1; cvt.u32.u64 %0, t; }" : "=r"(a) : "l"(p));
    return a;
}
__device__ __forceinline__ void ldsm4(uint32_t* r, uint32_t addr) {
    asm volatile("ldmatrix.sync.aligned.m8n8.x4.shared.b16 {%0,%1,%2,%3}, [%4];"
        : "=r"(r[0]), "=r"(r[1]), "=r"(r[2]), "=r"(r[3]) : "r"(addr));
}
__device__ __forceinline__ void mma16816(float* d, const uint32_t* a, uint32_t b0, uint32_t b1) {
    asm volatile("mma.sync.aligned.m16n8k16.row.col.f32.bf16.bf16.f32 "
        "{%0,%1,%2,%3}, {%4,%5,%6,%7}, {%8,%9}, {%0,%1,%2,%3};"
        : "+f"(d[0]), "+f"(d[1]), "+f"(d[2]), "+f"(d[3])
        : "r"(a[0]), "r"(a[1]), "r"(a[2]), "r"(a[3]), "r"(b0), "r"(b1));
}
__device__ __forceinline__ void split_bf16(float v, __nv_bfloat16& h, __nv_bfloat16& l) {
    h = __float2bfloat16(v);
    l = __float2bfloat16(v - __bfloat162float(h));
}
__device__ __forceinline__ uint32_t pack_exp(float e) {
    __nv_bfloat16 h, l; split_bf16(e, h, l);
    return (uint32_t)__bfloat16_as_ushort(h) | ((uint32_t)__bfloat16_as_ushort(l) << 16);
}

// A-fragment address (m16k16, [m][k] row-major, pitch 72 bf16)
__device__ __forceinline__ uint32_t a_addr(uint32_t base, int row0, int k0, int lane) {
    int r = row0 + (lane & 15), c = k0 + ((lane >> 4) << 3);
    return base + (uint32_t)((r * 72 + c) * 2);
}
// B-fragment x4 address (two n8k16 tiles, B stored [n][k] row-major, pitch 72)
__device__ __forceinline__ uint32_t b_addr(uint32_t base, int n0, int k0, int lane) {
    int r = n0 + (lane & 7) + ((lane >> 4) << 3), c = k0 + (((lane >> 3) & 1) << 3);
    return base + (uint32_t)((r * 72 + c) * 2);
}

// ---------------- scratch ----------------
__device__ __nv_bfloat16 d_Qh[BB*HW_*64],  d_Ql[BB*HW_*64];
__device__ __nv_bfloat16 d_Kh[BB*PHW_*64], d_Kl[BB*PHW_*64];
__device__ __nv_bfloat16 d_Vh[BB*C_*PHW_], d_Vl[BB*C_*PHW_];
__device__ uint32_t      d_Pp[(size_t)BB*HW_*PHW_];   // packed exp: hi | lo<<16
__device__ float         d_rinv[BB*HW_];
__device__ float         d_y[BB*HW_*C_];

// ======================================================================
// fp32 conv kernels (epilogues emit bf16 hi/lo)
// ======================================================================
union SMemConv { struct { float Xs[32][128]; float Ws[64][33]; } in; float Res[128][65]; };
union SMemQK   { struct { float As[32][129]; float Bs[64][33]; } in; float Res[128][65]; };

// MODE 0: g conv -> V [b][c][m] ; MODE 1: phi conv -> K [b][m][64]
template<int MODE>
__global__ __launch_bounds__(256) void conv_pool_kernel(
    const float* __restrict__ x, const float* __restrict__ w, const float* __restrict__ bias,
    __nv_bfloat16* __restrict__ oh, __nv_bfloat16* __restrict__ ol, int cin_off, int cin)
{
    __shared__ SMemConv sm;
    const int b = blockIdx.z, ph = blockIdx.y, o0 = blockIdx.x * 64;
    const int tid = threadIdx.x, ocg = tid & 7, pxg = tid >> 3;
    const float* xb = x + ((size_t)b * C_ + cin_off) * HW_ + ph * 128;
    float acc[4][8];
#pragma unroll
    for (int i = 0; i < 4; i++)
#pragma unroll
        for (int j = 0; j < 8; j++) acc[i][j] = 0.f;
    for (int kc = 0; kc < cin; kc += 32) {
#pragma unroll
        for (int t = 0; t < 16; t++) {
            int e = tid + t * 256, c = e >> 7, p = e & 127;
            sm.in.Xs[c][p] = xb[(size_t)(kc + c) * HW_ + p];
        }
#pragma unroll
        for (int t = 0; t < 8; t++) {
            int e = tid + t * 256, o = e >> 5, c = e & 31;
            sm.in.Ws[o][c] = w[(size_t)(o0 + o) * cin + kc + c];
        }
        __syncthreads();
#pragma unroll
        for (int k = 0; k < 32; k++) {
            float xv[4], wv[8];
#pragma unroll
            for (int i = 0; i < 4; i++) xv[i] = sm.in.Xs[k][pxg + 32 * i];
#pragma unroll
            for (int j = 0; j < 8; j++) wv[j] = sm.in.Ws[ocg + 8 * j][k];
#pragma unroll
            for (int i = 0; i < 4; i++)
#pragma unroll
                for (int j = 0; j < 8; j++) acc[i][j] += xv[i] * wv[j];
        }
        __syncthreads();
    }
#pragma unroll
    for (int i = 0; i < 4; i++)
#pragma unroll
        for (int j = 0; j < 8; j++) sm.Res[pxg + 32 * i][ocg + 8 * j] = acc[i][j];
    __syncthreads();
#pragma unroll
    for (int t = 0; t < 8; t++) {
        int e = tid + t * 256, pw, o;
        if (MODE == 0) { pw = e & 31; o = e >> 5; } else { o = e & 63; pw = e >> 6; }
        float v = fmaxf(fmaxf(sm.Res[2*pw][o], sm.Res[2*pw+1][o]),
                        fmaxf(sm.Res[64+2*pw][o], sm.Res[65+2*pw][o])) + bias[o0 + o];
        __nv_bfloat16 h, l; split_bf16(v, h, l);
        size_t oidx = (MODE == 0) ? ((size_t)b * C_ + o0 + o) * PHW_ + ph * 32 + pw
                                  : ((size_t)b * PHW_ + ph * 32 + pw) * 64 + o;
        oh[oidx] = h; ol[oidx] = l;
    }
}

__global__ __launch_bounds__(256) void conv_theta_kernel(
    const float* __restrict__ x, const float* __restrict__ w, const float* __restrict__ bias,
    __nv_bfloat16* __restrict__ oh, __nv_bfloat16* __restrict__ ol)
{
    __shared__ SMemConv sm;
    const int b = blockIdx.y, pt = blockIdx.x;
    const int tid = threadIdx.x, ocg = tid & 7, pxg = tid >> 3;
    const float* xb = x + (size_t)b * C_ * HW_ + pt * 128;
    float acc[4][8];
#pragma unroll
    for (int i = 0; i < 4; i++)
#pragma unroll
        for (int j = 0; j < 8; j++) acc[i][j] = 0.f;
    for (int kc = 0; kc < 64; kc += 32) {
#pragma unroll
        for (int t = 0; t < 16; t++) {
            int e = tid + t * 256, c = e >> 7, p = e & 127;
            sm.in.Xs[c][p] = xb[(size_t)(kc + c) * HW_ + p];
        }
#pragma unroll
        for (int t = 0; t < 8; t++) {
            int e = tid + t * 256, o = e >> 5, c = e & 31;
            sm.in.Ws[o][c] = w[(size_t)o * 64 + kc + c];
        }
        __syncthreads();
#pragma unroll
        for (int k = 0; k < 32; k++) {
            float xv[4], wv[8];
#pragma unroll
            for (int i = 0; i < 4; i++) xv[i] = sm.in.Xs[k][pxg + 32 * i];
#pragma unroll
            for (int j = 0; j < 8; j++) wv[j] = sm.in.Ws[ocg + 8 * j][k];
#pragma unroll
            for (int i = 0; i < 4; i++)
#pragma unroll
                for (int j = 0; j < 8; j++) acc[i][j] += xv[i] * wv[j];
        }
        __syncthreads();
    }
#pragma unroll
    for (int i = 0; i < 4; i++)
#pragma unroll
        for (int j = 0; j < 8; j++) sm.Res[pxg + 32 * i][ocg + 8 * j] = acc[i][j];
    __syncthreads();
#pragma unroll
    for (int t = 0; t < 32; t++) {
        int e = tid + t * 256, p = e >> 6, o = e & 63;
        float v = sm.Res[p][o] + bias[o];
        __nv_bfloat16 h, l; split_bf16(v, h, l);
        size_t oidx = ((size_t)b * HW_ + pt * 128 + p) * 64 + o;
        oh[oidx] = h; ol[oidx] = l;
    }
}

// ======================================================================
// qk_mma: S = Q K^T (split-bf16 mma.sync) + fused exp/rowsum epilogue.
// grid (32, 8), block 256 (8 warps 4x2; warp tile 32 rows x 64 cols).
// Loops 8 chunks of 128 K-rows. smem (bf16, pitch 72):
//   Qh@0 Ql@9216 Kh@18432 Kl@27648 (elements); rs float[2][128] @ byte 73728
// ======================================================================
static constexpr int QK_SMEM = 73728 + 1024;

__global__ __launch_bounds__(256) void qk_mma_kernel(
    const __nv_bfloat16* __restrict__ Qh, const __nv_bfloat16* __restrict__ Ql,
    const __nv_bfloat16* __restrict__ Kh, const __nv_bfloat16* __restrict__ Kl,
    uint32_t* __restrict__ Pp, float* __restrict__ rinv)
{
    extern __shared__ char smem[];
    __nv_bfloat16* sQh = (__nv_bfloat16*)smem;
    __nv_bfloat16* sQl = sQh + 9216;
    __nv_bfloat16* sKh = sQh + 18432;
    __nv_bfloat16* sKl = sQh + 27648;
    float* rs = (float*)(smem + 73728);   // [2][128]
    const uint32_t sbQh = smem_to_u32(sQh), sbQl = smem_to_u32(sQl);
    const uint32_t sbKh = smem_to_u32(sKh), sbKl = smem_to_u32(sKl);

    const int tid = threadIdx.x, lane = tid & 31, wid = tid >> 5;
    const int wm = wid & 3, wn = wid >> 2;            // 4 x 2 warp grid
    const int b = blockIdx.y, n0 = blockIdx.x * 128;

    // load Q tile (128 x 64 hi/lo)
    {
        const __nv_bfloat16* gqh = Qh + ((size_t)b * HW_ + n0) * 64;
        const __nv_bfloat16* gql = Ql + ((size_t)b * HW_ + n0) * 64;
        for (int idx = tid; idx < 1024; idx += 256) {
            int r = idx >> 3, u = idx & 7;
            *(uint4*)(sQh + r * 72 + u * 8) = *(const uint4*)(gqh + r * 64 + u * 8);
            *(uint4*)(sQl + r * 72 + u * 8) = *(const uint4*)(gql + r * 64 + u * 8);
        }
    }

    float rsum[2][2] = {{0.f, 0.f}, {0.f, 0.f}};

    for (int ck = 0; ck < 8; ck++) {
        const int m0 = ck * 128;
        __syncthreads();
        {   // load K chunk (128 x 64 hi/lo)
            const __nv_bfloat16* gkh = Kh + ((size_t)b * PHW_ + m0) * 64;
            const __nv_bfloat16* gkl = Kl + ((size_t)b * PHW_ + m0) * 64;
            for (int idx = tid; idx < 1024; idx += 256) {
                int r = idx >> 3, u = idx & 7;
                *(uint4*)(sKh + r * 72 + u * 8) = *(const uint4*)(gkh + r * 64 + u * 8);
                *(uint4*)(sKl + r * 72 + u * 8) = *(const uint4*)(gkl + r * 64 + u * 8);
            }
        }
        __syncthreads();

        float acc[2][8][4];
#pragma unroll
        for (int mt = 0; mt < 2; mt++)
#pragma unroll
            for (int nt = 0; nt < 8; nt++)
#pragma unroll
                for (int e = 0; e < 4; e++) acc[mt][nt][e] = 0.f;

#pragma unroll
        for (int ks = 0; ks < 4; ks++) {
            const int k0 = ks * 16;
            uint32_t ah[2][4], al[2][4];
            ldsm4(ah[0], a_addr(sbQh, wm * 32,      k0, lane));
            ldsm4(ah[1], a_addr(sbQh, wm * 32 + 16, k0, lane));
            ldsm4(al[0], a_addr(sbQl, wm * 32,      k0, lane));
            ldsm4(al[1], a_addr(sbQl, wm * 32 + 16, k0, lane));
#pragma unroll
            for (int g = 0; g < 4; g++) {
                uint32_t bh[4], bl[4];
                ldsm4(bh, b_addr(sbKh, wn * 64 + g * 16, k0, lane));
                ldsm4(bl, b_addr(sbKl, wn * 64 + g * 16, k0, lane));
#pragma unroll
                for (int mt = 0; mt < 2; mt++) {
                    mma16816(acc[mt][g*2],   ah[mt], bh[0], bh[1]);
                    mma16816(acc[mt][g*2],   ah[mt], bl[0], bl[1]);
                    mma16816(acc[mt][g*2],   al[mt], bh[0], bh[1]);
                    mma16816(acc[mt][g*2+1], ah[mt], bh[2], bh[3]);
                    mma16816(acc[mt][g*2+1], ah[mt], bl[2], bl[3]);
                    mma16816(acc[mt][g*2+1], al[mt], bh[2], bh[3]);
                }
            }
        }

        // epilogue: exp, accumulate row sums, pack & store
#pragma unroll
        for (int mt = 0; mt < 2; mt++) {
            const int row = n0 + wm * 32 + mt * 16 + (lane >> 2);
#pragma unroll
            for (int nt = 0; nt < 8; nt++) {
                float e0 = __expf(acc[mt][nt][0]);
                float e1 = __expf(acc[mt][nt][1]);
                float e2 = __expf(acc[mt][nt][2]);
                float e3 = __expf(acc[mt][nt][3]);
                rsum[mt][0] += e0 + e1;
                rsum[mt][1] += e2 + e3;
                const int col = m0 + wn * 64 + nt * 8 + (lane & 3) * 2;
                *(uint2*)&Pp[((size_t)b * HW_ + row) * PHW_ + col] =
                    make_uint2(pack_exp(e0), pack_exp(e1));
                *(uint2*)&Pp[((size_t)b * HW_ + row + 8) * PHW_ + col] =
                    make_uint2(pack_exp(e2), pack_exp(e3));
            }
        }
    }

    // combine row sums: quad shfl then across the two warpN columns via smem
#pragma unroll
    for (int mt = 0; mt < 2; mt++)
#pragma unroll
        for (int hh = 0; hh < 2; hh++) {
            float s = rsum[mt][hh];
            s += __shfl_xor_sync(0xffffffffu, s, 1);
            s += __shfl_xor_sync(0xffffffffu, s, 2);
            if ((lane & 3) == 0)
                rs[wn * 128 + wm * 32 + mt * 16 + hh * 8 + (lane >> 2)] = s;
        }
    __syncthreads();
    if (tid < 128)
        rinv[(size_t)b * HW_ + n0 + tid] = 1.f / (rs[tid] + rs[128 + tid]);
}

// ======================================================================
// pv_mma: Y = exp(S) @ V * rinv. grid (32, 8), block 512 (16 warps 4x4;
// warp tile 32 rows x 64 cols of 256). 16 k-chunks of 64.
// smem (bf16, pitch 72): Ah@0 Al@9216 Bh@18432 Bl@36864 (elements)
// ======================================================================
static constexpr int PV_SMEM = (18432 + 36864) * 2;   // 110592 bytes

__global__ __launch_bounds__(512) void pv_mma_kernel(
    const uint32_t* __restrict__ Pp,
    const __nv_bfloat16* __restrict__ Vh, const __nv_bfloat16* __restrict__ Vl,
    const float* __restrict__ rinv, float* __restrict__ Y)
{
    extern __shared__ char smem[];
    __nv_bfloat16* sAh = (__nv_bfloat16*)smem;
    __nv_bfloat16* sAl = sAh + 9216;
    __nv_bfloat16* sBh = sAh + 18432;
    __nv_bfloat16* sBl = sAh + 36864;
    const uint32_t sbAh = smem_to_u32(sAh), sbAl = smem_to_u32(sAl);
    const uint32_t sbBh = smem_to_u32(sBh), sbBl = smem_to_u32(sBl);

    const int tid = threadIdx.x, lane = tid & 31, wid = tid >> 5;
    const int wm = wid & 3, wn = wid >> 2;            // 4 x 4 warp grid
    const int b = blockIdx.y, n0 = blockIdx.x * 128;

    float acc[2][8][4];
#pragma unroll
    for (int mt = 0; mt < 2; mt++)
#pragma unroll
        for (int nt = 0; nt < 8; nt++)
#pragma unroll
            for (int e = 0; e < 4; e++) acc[mt][nt][e] = 0.f;

    for (int ck = 0; ck < 16; ck++) {
        const int m0 = ck * 64;
        __syncthreads();
        {   // A: P chunk 128 rows x 64 packed u32 -> unpack hi/lo (paired stores)
            const uint32_t* gp = Pp + ((size_t)b * HW_ + n0) * PHW_ + m0;
            for (int idx = tid; idx < 4096; idx += 512) {
                int r = idx >> 5, c2 = (idx & 31) * 2;
                uint32_t v0 = gp[(size_t)r * PHW_ + c2];
                uint32_t v1 = gp[(size_t)r * PHW_ + c2 + 1];
                *(uint32_t*)(sAh + r * 72 + c2) = (v0 & 0xffffu) | (v1 << 16);
                *(uint32_t*)(sAl + r * 72 + c2) = (v0 >> 16) | (v1 & 0xffff0000u);
            }
            // B: V chunk 256 rows (channels) x 64 m
            const __nv_bfloat16* gvh = Vh + (size_t)b * C_ * PHW_ + m0;
            const __nv_bfloat16* gvl = Vl + (size_t)b * C_ * PHW_ + m0;
            for (int idx = tid; idx < 2048; idx += 512) {
                int r = idx >> 3, u = idx & 7;
                *(uint4*)(sBh + r * 72 + u * 8) = *(const uint4*)(gvh + (size_t)r * PHW_ + u * 8);
                *(uint4*)(sBl + r * 72 + u * 8) = *(const uint4*)(gvl + (size_t)r * PHW_ + u * 8);
            }
        }
        __syncthreads();

#pragma unroll
        for (int ks = 0; ks < 4; ks++) {
            const int k0 = ks * 16;
            uint32_t ah[2][4], al[2][4];
            ldsm4(ah[0], a_addr(sbAh, wm * 32,      k0, lane));
            ldsm4(ah[1], a_addr(sbAh, wm * 32 + 16, k0, lane));
            ldsm4(al[0], a_addr(sbAl, wm * 32,      k0, lane));
            ldsm4(al[1], a_addr(sbAl, wm * 32 + 16, k0, lane));
#pragma unroll
            for (int g = 0; g < 4; g++) {
                uint32_t bh[4], bl[4];
                ldsm4(bh, b_addr(sbBh, wn * 64 + g * 16, k0, lane));
                ldsm4(bl, b_addr(sbBl, wn * 64 + g * 16, k0, lane));
#pragma unroll
                for (int mt = 0; mt < 2; mt++) {
                    mma16816(acc[mt][g*2],   ah[mt], bh[0], bh[1]);
                    mma16816(acc[mt][g*2],   ah[mt], bl[0], bl[1]);
                    mma16816(acc[mt][g*2],   al[mt], bh[0], bh[1]);
                    mma16816(acc[mt][g*2+1], ah[mt], bh[2], bh[3]);
                    mma16816(acc[mt][g*2+1], ah[mt], bl[2], bl[3]);
                    mma16816(acc[mt][g*2+1], al[mt], bh[2], bh[3]);
                }
            }
        }
    }

    // epilogue: scale by 1/rowsum, store fp32 Y [row][c]
#pragma unroll
    for (int mt = 0; mt < 2; mt++) {
        const int r0 = n0 + wm * 32 + mt * 16 + (lane >> 2);
        const float i0 = rinv[(size_t)b * HW_ + r0];
        const float i1 = rinv[(size_t)b * HW_ + r0 + 8];
#pragma unroll
        for (int nt = 0; nt < 8; nt++) {
            const int col = wn * 64 + nt * 8 + (lane & 3) * 2;
            float2 v0 = make_float2(acc[mt][nt][0] * i0, acc[mt][nt][1] * i0);
            float2 v1 = make_float2(acc[mt][nt][2] * i1, acc[mt][nt][3] * i1);
            *(float2*)&Y[((size_t)b * HW_ + r0) * C_ + col] = v0;
            *(float2*)&Y[((size_t)b * HW_ + r0 + 8) * C_ + col] = v1;
        }
    }
}

// ======================================================================
// final: out = BN(Y @ W^T + Wb) + x  (fp32)
// ======================================================================
__global__ __launch_bounds__(256) void final_kernel(
    const float* __restrict__ Y, const float* __restrict__ Ww, const float* __restrict__ Wb,
    const float* __restrict__ gamma, const float* __restrict__ beta,
    const float* __restrict__ mean, const float* __restrict__ var,
    const float* __restrict__ x, float* __restrict__ out)
{
    __shared__ SMemQK sm;
    const int b = blockIdx.z, nt = blockIdx.y, o0 = blockIdx.x * 64;
    const int tid = threadIdx.x, ocg = tid & 7, pxg = tid >> 3;
    const float* Yb = Y + ((size_t)b * HW_ + nt * 128) * C_;
    float acc[4][8];
#pragma unroll
    for (int i = 0; i < 4; i++)
#pragma unroll
        for (int j = 0; j < 8; j++) acc[i][j] = 0.f;
    for (int kc = 0; kc < C_; kc += 32) {
#pragma unroll
        for (int t = 0; t < 16; t++) {
            int e = tid + t * 256, p = e >> 5, k = e & 31;
            sm.in.As[k][p] = Yb[(size_t)p * C_ + kc + k];
        }
#pragma unroll
        for (int t = 0; t < 8; t++) {
            int e = tid + t * 256, o = e >> 5, k = e & 31;
            sm.in.Bs[o][k] = Ww[(size_t)(o0 + o) * C_ + kc + k];
        }
        __syncthreads();
#pragma unroll
        for (int k = 0; k < 32; k++) {
            float xv[4], wv[8];
#pragma unroll
            for (int i = 0; i < 4; i++) xv[i] = sm.in.As[k][pxg + 32 * i];
#pragma unroll
            for (int j = 0; j < 8; j++) wv[j] = sm.in.Bs[ocg + 8 * j][k];
#pragma unroll
            for (int i = 0; i < 4; i++)
#pragma unroll
                for (int j = 0; j < 8; j++) acc[i][j] += xv[i] * wv[j];
        }
        __syncthreads();
    }
#pragma unroll
    for (int i = 0; i < 4; i++)
#pragma unroll
        for (int j = 0; j < 8; j++) sm.Res[pxg + 32 * i][ocg + 8 * j] = acc[i][j];
    __syncthreads();
#pragma unroll
    for (int t = 0; t < 32; t++) {
        int e = tid + t * 256, o = e >> 7, p = e & 127;
        int oc = o0 + o;
        float scale = gamma[oc] * rsqrtf(var[oc] + EPS_);
        size_t gidx = ((size_t)b * C_ + oc) * HW_ + nt * 128 + p;
        out[gidx] = (sm.Res[p][o] + Wb[oc] - mean[oc]) * scale + beta[oc] + x[gidx];
    }
}

// ======================================================================
extern "C" void kernel_launch(void* const* d_in, const int* in_sizes, int n_in,
                              void* d_out, int out_size)
{
    const float* x       = (const float*)d_in[0];
    const float* g_w     = (const float*)d_in[1];
    const float* g_b     = (const float*)d_in[2];
    const float* theta_w = (const float*)d_in[3];
    const float* theta_b = (const float*)d_in[4];
    const float* phi_w   = (const float*)d_in[5];
    const float* phi_b   = (const float*)d_in[6];
    const float* W_w     = (const float*)d_in[7];
    const float* W_b     = (const float*)d_in[8];
    const float* bn_g    = (const float*)d_in[9];
    const float* bn_b    = (const float*)d_in[10];
    const float* bn_m    = (const float*)d_in[11];
    const float* bn_v    = (const float*)d_in[12];
    float* out = (float*)d_out;

    __nv_bfloat16 *Qh, *Ql, *Kh, *Kl, *Vh, *Vl;
    uint32_t* Pp; float *rv, *y;
    cudaGetSymbolAddress((void**)&Qh, d_Qh);
    cudaGetSymbolAddress((void**)&Ql, d_Ql);
    cudaGetSymbolAddress((void**)&Kh, d_Kh);
    cudaGetSymbolAddress((void**)&Kl, d_Kl);
    cudaGetSymbolAddress((void**)&Vh, d_Vh);
    cudaGetSymbolAddress((void**)&Vl, d_Vl);
    cudaGetSymbolAddress((void**)&Pp, d_Pp);
    cudaGetSymbolAddress((void**)&rv, d_rinv);
    cudaGetSymbolAddress((void**)&y,  d_y);

    cudaFuncSetAttribute(qk_mma_kernel, cudaFuncAttributeMaxDynamicSharedMemorySize, QK_SMEM);
    cudaFuncSetAttribute(pv_mma_kernel, cudaFuncAttributeMaxDynamicSharedMemorySize, PV_SMEM);

    conv_pool_kernel<0><<<dim3(4, 32, BB), 256>>>(x, g_w, g_b, Vh, Vl, 0, 256);
    conv_pool_kernel<1><<<dim3(1, 32, BB), 256>>>(x, phi_w, phi_b, Kh, Kl, 64, 192);
    conv_theta_kernel<<<dim3(32, BB), 256>>>(x, theta_w, theta_b, Qh, Ql);
    qk_mma_kernel<<<dim3(32, BB), 256, QK_SMEM>>>(Qh, Ql, Kh, Kl, Pp, rv);
    pv_mma_kernel<<<dim3(32, BB), 512, PV_SMEM>>>(Pp, Vh, Vl, rv, y);
    final_kernel<<<dim3(4, 32, BB), 256>>>(y, W_w, W_b, bn_g, bn_b, bn_m, bn_v, x, out);
}

// round 6
// speedup vs baseline: 1.8859x; 1.1461x over previous
#include <cuda_runtime.h>
#include <cuda_bf16.h>
#include <cstdint>

#define BB 8
#define C_ 256
#define HW_ 4096
#define PHW_ 1024
#define EPS_ 1e-5f

// ---------------- mma.sync helpers ----------------
__device__ __forceinline__ uint32_t smem_to_u32(const void* p) {
    uint32_t a;
    asm("{ .reg .u64 t; cvta.to.shared.u64 t, %1; cvt.u32.u64 %0, t; }" : "=r"(a) : "l"(p));
    return a;
}
__device__ __forceinline__ void ldsm4(uint32_t* r, uint32_t addr) {
    asm volatile("ldmatrix.sync.aligned.m8n8.x4.shared.b16 {%0,%1,%2,%3}, [%4];"
        : "=r"(r[0]), "=r"(r[1]), "=r"(r[2]), "=r"(r[3]) : "r"(addr));
}
__device__ __forceinline__ void ldsm4t(uint32_t* r, uint32_t addr) {
    asm volatile("ldmatrix.sync.aligned.m8n8.x4.trans.shared.b16 {%0,%1,%2,%3}, [%4];"
        : "=r"(r[0]), "=r"(r[1]), "=r"(r[2]), "=r"(r[3]) : "r"(addr));
}
__device__ __forceinline__ void mma16816(float* d, const uint32_t* a, uint32_t b0, uint32_t b1) {
    asm volatile("mma.sync.aligned.m16n8k16.row.col.f32.bf16.bf16.f32 "
        "{%0,%1,%2,%3}, {%4,%5,%6,%7}, {%8,%9}, {%0,%1,%2,%3};"
        : "+f"(d[0]), "+f"(d[1]), "+f"(d[2]), "+f"(d[3])
        : "r"(a[0]), "r"(a[1]), "r"(a[2]), "r"(a[3]), "r"(b0), "r"(b1));
}
__device__ __forceinline__ void split_bf16(float v, __nv_bfloat16& h, __nv_bfloat16& l) {
    h = __float2bfloat16(v);
    l = __float2bfloat16(v - __bfloat162float(h));
}
__device__ __forceinline__ uint32_t pack_exp(float e) {
    __nv_bfloat16 h, l; split_bf16(e, h, l);
    return (uint32_t)__bfloat16_as_ushort(h) | ((uint32_t)__bfloat16_as_ushort(l) << 16);
}

// A-fragment (m16k16) from [m][k] row-major smem, pitch 72
__device__ __forceinline__ uint32_t a_addr(uint32_t base, int row0, int k0, int lane) {
    int r = row0 + (lane & 15), c = k0 + ((lane >> 4) << 3);
    return base + (uint32_t)((r * 72 + c) * 2);
}
// A-fragment (m16k16) from [k][m] storage via trans-ldmatrix, pitch P
__device__ __forceinline__ uint32_t at_addr(uint32_t base, int m0, int k0, int lane, int P) {
    int t = lane >> 3;
    int m = m0 + ((t & 1) << 3);
    int k = k0 + ((t >> 1) << 3) + (lane & 7);
    return base + (uint32_t)((k * P + m) * 2);
}
// B-fragment x4 (two n8k16 tiles) from [n][k] row-major smem, pitch 72
__device__ __forceinline__ uint32_t b_addr(uint32_t base, int n0, int k0, int lane) {
    int r = n0 + (lane & 7) + ((lane >> 4) << 3), c = k0 + (((lane >> 3) & 1) << 3);
    return base + (uint32_t)((r * 72 + c) * 2);
}

// ---------------- scratch ----------------
__device__ __nv_bfloat16 d_xh[BB*C_*HW_], d_xl[BB*C_*HW_];
__device__ __nv_bfloat16 d_Wch[384*256],  d_Wcl[384*256];     // packed conv weights
__device__ float         d_bc[384];                           // packed conv biases
__device__ __nv_bfloat16 d_Wfh[256*256],  d_Wfl[256*256];     // final conv weights
__device__ __nv_bfloat16 d_Qh[BB*HW_*64],  d_Ql[BB*HW_*64];
__device__ __nv_bfloat16 d_Kh[BB*PHW_*64], d_Kl[BB*PHW_*64];
__device__ __nv_bfloat16 d_Vh[BB*C_*PHW_], d_Vl[BB*C_*PHW_];  // V [b][c][m]
__device__ uint32_t      d_Pp[(size_t)BB*HW_*PHW_];           // packed exp hi|lo<<16
__device__ float         d_rinv[BB*HW_];
__device__ __nv_bfloat16 d_Yh[BB*HW_*C_],  d_Yl[BB*HW_*C_];   // Y [n][c]

// ======================================================================
// xsplit: x fp32 -> hi/lo bf16 (same [b][c][hw] layout)
// ======================================================================
__global__ __launch_bounds__(256) void xsplit_kernel(
    const float* __restrict__ x, __nv_bfloat16* __restrict__ xh, __nv_bfloat16* __restrict__ xl)
{
    size_t i = ((size_t)blockIdx.x * 256 + threadIdx.x) * 4;
    float4 v = *(const float4*)(x + i);
    __nv_bfloat16 h0,l0,h1,l1,h2,l2,h3,l3;
    split_bf16(v.x,h0,l0); split_bf16(v.y,h1,l1);
    split_bf16(v.z,h2,l2); split_bf16(v.w,h3,l3);
    uint2 ph = make_uint2((uint32_t)__bfloat16_as_ushort(h0) | ((uint32_t)__bfloat16_as_ushort(h1)<<16),
                          (uint32_t)__bfloat16_as_ushort(h2) | ((uint32_t)__bfloat16_as_ushort(h3)<<16));
    uint2 pl = make_uint2((uint32_t)__bfloat16_as_ushort(l0) | ((uint32_t)__bfloat16_as_ushort(l1)<<16),
                          (uint32_t)__bfloat16_as_ushort(l2) | ((uint32_t)__bfloat16_as_ushort(l3)<<16));
    *(uint2*)(xh + i) = ph;
    *(uint2*)(xl + i) = pl;
}

// ======================================================================
// wpack_conv: combine g/theta/phi weights -> [384][256] bf16 hi/lo + bias
// oc 0..255: g ; 256..319: theta (k<64) ; 320..383: phi (k>=64)
// ======================================================================
__global__ void wpack_conv_kernel(
    const float* __restrict__ g_w, const float* __restrict__ g_b,
    const float* __restrict__ th_w, const float* __restrict__ th_b,
    const float* __restrict__ ph_w, const float* __restrict__ ph_b,
    __nv_bfloat16* __restrict__ Wh, __nv_bfloat16* __restrict__ Wl, float* __restrict__ bc)
{
    int oc = blockIdx.x, k = threadIdx.x;
    float v;
    if (oc < 256)       v = g_w[oc * 256 + k];
    else if (oc < 320)  v = (k < 64) ? th_w[(oc - 256) * 64 + k] : 0.f;
    else                v = (k >= 64) ? ph_w[(oc - 320) * 192 + (k - 64)] : 0.f;
    __nv_bfloat16 h, l; split_bf16(v, h, l);
    Wh[oc * 256 + k] = h; Wl[oc * 256 + k] = l;
    if (k == 0)
        bc[oc] = (oc < 256) ? g_b[oc] : (oc < 320) ? th_b[oc - 256] : ph_b[oc - 320];
}

__global__ void wpack_final_kernel(const float* __restrict__ w,
    __nv_bfloat16* __restrict__ Wh, __nv_bfloat16* __restrict__ Wl)
{
    int i = blockIdx.x * 256 + threadIdx.x;
    __nv_bfloat16 h, l; split_bf16(w[i], h, l);
    Wh[i] = h; Wl[i] = l;
}

// ======================================================================
// conv_mma: all 3 input convs in one. grid (3, 32, 8), block 256.
// CTA: 128 px x 128 oc, K=256 in 4 chunks of 64.
// A = x^T via trans-ldmatrix from [c][p] smem (pitch 136);
// B = W [oc][k] non-trans (pitch 72).
// smem: sXh@0(17408B) sXl@17408 sWh@34816(18432B) sWl@53248 ; total 71680
// epilogue stages fp32 [128][132] (union at 0)
// ======================================================================
static constexpr int CONV_SMEM = 71680;

__global__ __launch_bounds__(256) void conv_mma_kernel(
    const __nv_bfloat16* __restrict__ xh, const __nv_bfloat16* __restrict__ xl,
    const __nv_bfloat16* __restrict__ Wh, const __nv_bfloat16* __restrict__ Wl,
    const float* __restrict__ bc,
    __nv_bfloat16* __restrict__ Vh, __nv_bfloat16* __restrict__ Vl,
    __nv_bfloat16* __restrict__ Qh, __nv_bfloat16* __restrict__ Ql,
    __nv_bfloat16* __restrict__ Kh, __nv_bfloat16* __restrict__ Kl)
{
    extern __shared__ char smem[];
    __nv_bfloat16* sXh = (__nv_bfloat16*)smem;           // [64][136]
    __nv_bfloat16* sXl = sXh + 8704;
    __nv_bfloat16* sWh = sXh + 17408;                    // [128][72]
    __nv_bfloat16* sWl = sXh + 17408 + 9216;
    float* sRes = (float*)smem;                          // [128][132] union
    const uint32_t sbXh = smem_to_u32(sXh), sbXl = smem_to_u32(sXl);
    const uint32_t sbWh = smem_to_u32(sWh), sbWl = smem_to_u32(sWl);

    const int tid = threadIdx.x, lane = tid & 31, wid = tid >> 5;
    const int wm = wid & 3, wn = wid >> 2;               // 4 x 2 warps
    const int b = blockIdx.z, pxt = blockIdx.y, oc0 = blockIdx.x * 128;

    float acc[2][8][4];
#pragma unroll
    for (int mt = 0; mt < 2; mt++)
#pragma unroll
        for (int nt = 0; nt < 8; nt++)
#pragma unroll
            for (int e = 0; e < 4; e++) acc[mt][nt][e] = 0.f;

    for (int ck = 0; ck < 4; ck++) {
        __syncthreads();
        {   // X chunk [64 c][128 p]
            const __nv_bfloat16* gxh = xh + ((size_t)b * C_ + ck * 64) * HW_ + pxt * 128;
            const __nv_bfloat16* gxl = xl + ((size_t)b * C_ + ck * 64) * HW_ + pxt * 128;
            for (int idx = tid; idx < 1024; idx += 256) {
                int r = idx >> 4, u = idx & 15;
                *(uint4*)(sXh + r * 136 + u * 8) = *(const uint4*)(gxh + (size_t)r * HW_ + u * 8);
                *(uint4*)(sXl + r * 136 + u * 8) = *(const uint4*)(gxl + (size_t)r * HW_ + u * 8);
            }
            // W chunk [128 oc][64 k]
            const __nv_bfloat16* gwh = Wh + (size_t)oc0 * 256 + ck * 64;
            const __nv_bfloat16* gwl = Wl + (size_t)oc0 * 256 + ck * 64;
            for (int idx = tid; idx < 1024; idx += 256) {
                int r = idx >> 3, u = idx & 7;
                *(uint4*)(sWh + r * 72 + u * 8) = *(const uint4*)(gwh + (size_t)r * 256 + u * 8);
                *(uint4*)(sWl + r * 72 + u * 8) = *(const uint4*)(gwl + (size_t)r * 256 + u * 8);
            }
        }
        __syncthreads();

#pragma unroll
        for (int ks = 0; ks < 4; ks++) {
            const int k0 = ks * 16;
            uint32_t ah[2][4], al[2][4];
            ldsm4t(ah[0], at_addr(sbXh, wm * 32,      k0, lane, 136));
            ldsm4t(ah[1], at_addr(sbXh, wm * 32 + 16, k0, lane, 136));
            ldsm4t(al[0], at_addr(sbXl, wm * 32,      k0, lane, 136));
            ldsm4t(al[1], at_addr(sbXl, wm * 32 + 16, k0, lane, 136));
#pragma unroll
            for (int g = 0; g < 4; g++) {
                uint32_t bh[4], bl[4];
                ldsm4(bh, b_addr(sbWh, wn * 64 + g * 16, k0, lane));
                ldsm4(bl, b_addr(sbWl, wn * 64 + g * 16, k0, lane));
#pragma unroll
                for (int mt = 0; mt < 2; mt++) {
                    mma16816(acc[mt][g*2],   ah[mt], bh[0], bh[1]);
                    mma16816(acc[mt][g*2],   ah[mt], bl[0], bl[1]);
                    mma16816(acc[mt][g*2],   al[mt], bh[0], bh[1]);
                    mma16816(acc[mt][g*2+1], ah[mt], bh[2], bh[3]);
                    mma16816(acc[mt][g*2+1], ah[mt], bl[2], bl[3]);
                    mma16816(acc[mt][g*2+1], al[mt], bh[2], bh[3]);
                }
            }
        }
    }

    // stage to smem fp32 [128 px][132]
    __syncthreads();
#pragma unroll
    for (int mt = 0; mt < 2; mt++) {
        const int row = wm * 32 + mt * 16 + (lane >> 2);
#pragma unroll
        for (int nt = 0; nt < 8; nt++) {
            const int col = wn * 64 + nt * 8 + (lane & 3) * 2;
            sRes[row * 132 + col]       = acc[mt][nt][0];
            sRes[row * 132 + col + 1]   = acc[mt][nt][1];
            sRes[(row+8) * 132 + col]   = acc[mt][nt][2];
            sRes[(row+8) * 132 + col+1] = acc[mt][nt][3];
        }
    }
    __syncthreads();

    if (oc0 < 256) {
        // g outputs: pool 2x2 -> V [b][oc][m]
        for (int t = tid; t < 32 * 128; t += 256) {
            int pw = t >> 7, lo = t & 127, oc = oc0 + lo;
            float v = fmaxf(fmaxf(sRes[(2*pw)*132 + lo], sRes[(2*pw+1)*132 + lo]),
                            fmaxf(sRes[(64+2*pw)*132 + lo], sRes[(65+2*pw)*132 + lo]))
                      + bc[oc];
            __nv_bfloat16 h, l; split_bf16(v, h, l);
            size_t oidx = ((size_t)b * C_ + oc) * PHW_ + pxt * 32 + pw;
            Vh[oidx] = h; Vl[oidx] = l;
        }
    } else {
        // theta (lo<64): no pool -> Q [n][64]
        for (int t = tid; t < 128 * 64; t += 256) {
            int p = t >> 6, o = t & 63;
            float v = sRes[p * 132 + o] + bc[256 + o];
            __nv_bfloat16 h, l; split_bf16(v, h, l);
            size_t oidx = ((size_t)b * HW_ + pxt * 128 + p) * 64 + o;
            Qh[oidx] = h; Ql[oidx] = l;
        }
        // phi (lo>=64): pool -> K [m][64]
        for (int t = tid; t < 32 * 64; t += 256) {
            int pw = t >> 6, o = t & 63, lo = 64 + o;
            float v = fmaxf(fmaxf(sRes[(2*pw)*132 + lo], sRes[(2*pw+1)*132 + lo]),
                            fmaxf(sRes[(64+2*pw)*132 + lo], sRes[(65+2*pw)*132 + lo]))
                      + bc[320 + o];
            __nv_bfloat16 h, l; split_bf16(v, h, l);
            size_t oidx = ((size_t)b * PHW_ + pxt * 32 + pw) * 64 + o;
            Kh[oidx] = h; Kl[oidx] = l;
        }
    }
}

// ======================================================================
// qk_mma: S = Q K^T + fused exp/rowsum (unchanged from R4)
// ======================================================================
static constexpr int QK_SMEM = 73728 + 1024;

__global__ __launch_bounds__(256) void qk_mma_kernel(
    const __nv_bfloat16* __restrict__ Qh, const __nv_bfloat16* __restrict__ Ql,
    const __nv_bfloat16* __restrict__ Kh, const __nv_bfloat16* __restrict__ Kl,
    uint32_t* __restrict__ Pp, float* __restrict__ rinv)
{
    extern __shared__ char smem[];
    __nv_bfloat16* sQh = (__nv_bfloat16*)smem;
    __nv_bfloat16* sQl = sQh + 9216;
    __nv_bfloat16* sKh = sQh + 18432;
    __nv_bfloat16* sKl = sQh + 27648;
    float* rs = (float*)(smem + 73728);
    const uint32_t sbQh = smem_to_u32(sQh), sbQl = smem_to_u32(sQl);
    const uint32_t sbKh = smem_to_u32(sKh), sbKl = smem_to_u32(sKl);

    const int tid = threadIdx.x, lane = tid & 31, wid = tid >> 5;
    const int wm = wid & 3, wn = wid >> 2;
    const int b = blockIdx.y, n0 = blockIdx.x * 128;

    {
        const __nv_bfloat16* gqh = Qh + ((size_t)b * HW_ + n0) * 64;
        const __nv_bfloat16* gql = Ql + ((size_t)b * HW_ + n0) * 64;
        for (int idx = tid; idx < 1024; idx += 256) {
            int r = idx >> 3, u = idx & 7;
            *(uint4*)(sQh + r * 72 + u * 8) = *(const uint4*)(gqh + r * 64 + u * 8);
            *(uint4*)(sQl + r * 72 + u * 8) = *(const uint4*)(gql + r * 64 + u * 8);
        }
    }

    float rsum[2][2] = {{0.f, 0.f}, {0.f, 0.f}};

    for (int ck = 0; ck < 8; ck++) {
        const int m0 = ck * 128;
        __syncthreads();
        {
            const __nv_bfloat16* gkh = Kh + ((size_t)b * PHW_ + m0) * 64;
            const __nv_bfloat16* gkl = Kl + ((size_t)b * PHW_ + m0) * 64;
            for (int idx = tid; idx < 1024; idx += 256) {
                int r = idx >> 3, u = idx & 7;
                *(uint4*)(sKh + r * 72 + u * 8) = *(const uint4*)(gkh + r * 64 + u * 8);
                *(uint4*)(sKl + r * 72 + u * 8) = *(const uint4*)(gkl + r * 64 + u * 8);
            }
        }
        __syncthreads();

        float acc[2][8][4];
#pragma unroll
        for (int mt = 0; mt < 2; mt++)
#pragma unroll
            for (int nt = 0; nt < 8; nt++)
#pragma unroll
                for (int e = 0; e < 4; e++) acc[mt][nt][e] = 0.f;

#pragma unroll
        for (int ks = 0; ks < 4; ks++) {
            const int k0 = ks * 16;
            uint32_t ah[2][4], al[2][4];
            ldsm4(ah[0], a_addr(sbQh, wm * 32,      k0, lane));
            ldsm4(ah[1], a_addr(sbQh, wm * 32 + 16, k0, lane));
            ldsm4(al[0], a_addr(sbQl, wm * 32,      k0, lane));
            ldsm4(al[1], a_addr(sbQl, wm * 32 + 16, k0, lane));
#pragma unroll
            for (int g = 0; g < 4; g++) {
                uint32_t bh[4], bl[4];
                ldsm4(bh, b_addr(sbKh, wn * 64 + g * 16, k0, lane));
                ldsm4(bl, b_addr(sbKl, wn * 64 + g * 16, k0, lane));
#pragma unroll
                for (int mt = 0; mt < 2; mt++) {
                    mma16816(acc[mt][g*2],   ah[mt], bh[0], bh[1]);
                    mma16816(acc[mt][g*2],   ah[mt], bl[0], bl[1]);
                    mma16816(acc[mt][g*2],   al[mt], bh[0], bh[1]);
                    mma16816(acc[mt][g*2+1], ah[mt], bh[2], bh[3]);
                    mma16816(acc[mt][g*2+1], ah[mt], bl[2], bl[3]);
                    mma16816(acc[mt][g*2+1], al[mt], bh[2], bh[3]);
                }
            }
        }

#pragma unroll
        for (int mt = 0; mt < 2; mt++) {
            const int row = n0 + wm * 32 + mt * 16 + (lane >> 2);
#pragma unroll
            for (int nt = 0; nt < 8; nt++) {
                float e0 = __expf(acc[mt][nt][0]);
                float e1 = __expf(acc[mt][nt][1]);
                float e2 = __expf(acc[mt][nt][2]);
                float e3 = __expf(acc[mt][nt][3]);
                rsum[mt][0] += e0 + e1;
                rsum[mt][1] += e2 + e3;
                const int col = m0 + wn * 64 + nt * 8 + (lane & 3) * 2;
                *(uint2*)&Pp[((size_t)b * HW_ + row) * PHW_ + col] =
                    make_uint2(pack_exp(e0), pack_exp(e1));
                *(uint2*)&Pp[((size_t)b * HW_ + row + 8) * PHW_ + col] =
                    make_uint2(pack_exp(e2), pack_exp(e3));
            }
        }
    }

#pragma unroll
    for (int mt = 0; mt < 2; mt++)
#pragma unroll
        for (int hh = 0; hh < 2; hh++) {
            float s = rsum[mt][hh];
            s += __shfl_xor_sync(0xffffffffu, s, 1);
            s += __shfl_xor_sync(0xffffffffu, s, 2);
            if ((lane & 3) == 0)
                rs[wn * 128 + wm * 32 + mt * 16 + hh * 8 + (lane >> 2)] = s;
        }
    __syncthreads();
    if (tid < 128)
        rinv[(size_t)b * HW_ + n0 + tid] = 1.f / (rs[tid] + rs[128 + tid]);
}

// ======================================================================
// pv_mma: Y = exp(S) @ V * rinv -> bf16 hi/lo Y [n][c]
// ======================================================================
static constexpr int PV_SMEM = (18432 + 36864) * 2;

__global__ __launch_bounds__(512) void pv_mma_kernel(
    const uint32_t* __restrict__ Pp,
    const __nv_bfloat16* __restrict__ Vh, const __nv_bfloat16* __restrict__ Vl,
    const float* __restrict__ rinv,
    __nv_bfloat16* __restrict__ Yh, __nv_bfloat16* __restrict__ Yl)
{
    extern __shared__ char smem[];
    __nv_bfloat16* sAh = (__nv_bfloat16*)smem;
    __nv_bfloat16* sAl = sAh + 9216;
    __nv_bfloat16* sBh = sAh + 18432;
    __nv_bfloat16* sBl = sAh + 36864;
    const uint32_t sbAh = smem_to_u32(sAh), sbAl = smem_to_u32(sAl);
    const uint32_t sbBh = smem_to_u32(sBh), sbBl = smem_to_u32(sBl);

    const int tid = threadIdx.x, lane = tid & 31, wid = tid >> 5;
    const int wm = wid & 3, wn = wid >> 2;
    const int b = blockIdx.y, n0 = blockIdx.x * 128;

    float acc[2][8][4];
#pragma unroll
    for (int mt = 0; mt < 2; mt++)
#pragma unroll
        for (int nt = 0; nt < 8; nt++)
#pragma unroll
            for (int e = 0; e < 4; e++) acc[mt][nt][e] = 0.f;

    for (int ck = 0; ck < 16; ck++) {
        const int m0 = ck * 64;
        __syncthreads();
        {
            const uint32_t* gp = Pp + ((size_t)b * HW_ + n0) * PHW_ + m0;
            for (int idx = tid; idx < 4096; idx += 512) {
                int r = idx >> 5, c2 = (idx & 31) * 2;
                uint32_t v0 = gp[(size_t)r * PHW_ + c2];
                uint32_t v1 = gp[(size_t)r * PHW_ + c2 + 1];
                *(uint32_t*)(sAh + r * 72 + c2) = (v0 & 0xffffu) | (v1 << 16);
                *(uint32_t*)(sAl + r * 72 + c2) = (v0 >> 16) | (v1 & 0xffff0000u);
            }
            const __nv_bfloat16* gvh = Vh + (size_t)b * C_ * PHW_ + m0;
            const __nv_bfloat16* gvl = Vl + (size_t)b * C_ * PHW_ + m0;
            for (int idx = tid; idx < 2048; idx += 512) {
                int r = idx >> 3, u = idx & 7;
                *(uint4*)(sBh + r * 72 + u * 8) = *(const uint4*)(gvh + (size_t)r * PHW_ + u * 8);
                *(uint4*)(sBl + r * 72 + u * 8) = *(const uint4*)(gvl + (size_t)r * PHW_ + u * 8);
            }
        }
        __syncthreads();

#pragma unroll
        for (int ks = 0; ks < 4; ks++) {
            const int k0 = ks * 16;
            uint32_t ah[2][4], al[2][4];
            ldsm4(ah[0], a_addr(sbAh, wm * 32,      k0, lane));
            ldsm4(ah[1], a_addr(sbAh, wm * 32 + 16, k0, lane));
            ldsm4(al[0], a_addr(sbAl, wm * 32,      k0, lane));
            ldsm4(al[1], a_addr(sbAl, wm * 32 + 16, k0, lane));
#pragma unroll
            for (int g = 0; g < 4; g++) {
                uint32_t bh[4], bl[4];
                ldsm4(bh, b_addr(sbBh, wn * 64 + g * 16, k0, lane));
                ldsm4(bl, b_addr(sbBl, wn * 64 + g * 16, k0, lane));
#pragma unroll
                for (int mt = 0; mt < 2; mt++) {
                    mma16816(acc[mt][g*2],   ah[mt], bh[0], bh[1]);
                    mma16816(acc[mt][g*2],   ah[mt], bl[0], bl[1]);
                    mma16816(acc[mt][g*2],   al[mt], bh[0], bh[1]);
                    mma16816(acc[mt][g*2+1], ah[mt], bh[2], bh[3]);
                    mma16816(acc[mt][g*2+1], ah[mt], bl[2], bl[3]);
                    mma16816(acc[mt][g*2+1], al[mt], bh[2], bh[3]);
                }
            }
        }
    }

    // epilogue: scale by 1/rowsum, split bf16 hi/lo, store Y [row][c]
#pragma unroll
    for (int mt = 0; mt < 2; mt++) {
        const int r0 = n0 + wm * 32 + mt * 16 + (lane >> 2);
        const float i0 = rinv[(size_t)b * HW_ + r0];
        const float i1 = rinv[(size_t)b * HW_ + r0 + 8];
#pragma unroll
        for (int nt = 0; nt < 8; nt++) {
            const int col = wn * 64 + nt * 8 + (lane & 3) * 2;
            float v0 = acc[mt][nt][0] * i0, v1 = acc[mt][nt][1] * i0;
            float v2 = acc[mt][nt][2] * i1, v3 = acc[mt][nt][3] * i1;
            __nv_bfloat16 h0,l0,h1,l1,h2,l2,h3,l3;
            split_bf16(v0,h0,l0); split_bf16(v1,h1,l1);
            split_bf16(v2,h2,l2); split_bf16(v3,h3,l3);
            *(uint32_t*)&Yh[((size_t)b * HW_ + r0) * C_ + col] =
                (uint32_t)__bfloat16_as_ushort(h0) | ((uint32_t)__bfloat16_as_ushort(h1) << 16);
            *(uint32_t*)&Yl[((size_t)b * HW_ + r0) * C_ + col] =
                (uint32_t)__bfloat16_as_ushort(l0) | ((uint32_t)__bfloat16_as_ushort(l1) << 16);
            *(uint32_t*)&Yh[((size_t)b * HW_ + r0 + 8) * C_ + col] =
                (uint32_t)__bfloat16_as_ushort(h2) | ((uint32_t)__bfloat16_as_ushort(h3) << 16);
            *(uint32_t*)&Yl[((size_t)b * HW_ + r0 + 8) * C_ + col] =
                (uint32_t)__bfloat16_as_ushort(l2) | ((uint32_t)__bfloat16_as_ushort(l3) << 16);
        }
    }
}

// ======================================================================
// final_mma: out = BN(Y @ W^T + Wb) + x. grid (2, 32, 8), block 256.
// A = Y [n][256] hi/lo non-trans, B = Wf [oc][256] hi/lo non-trans.
// smem: sAh@0 sAl@18432 sBh@36864 sBl@55296 (each [128][72]); total 73728
// staging fp32 [128][132] union at 0
// ======================================================================
static constexpr int FIN_SMEM = 73728;

__global__ __launch_bounds__(256) void final_mma_kernel(
    const __nv_bfloat16* __restrict__ Yh, const __nv_bfloat16* __restrict__ Yl,
    const __nv_bfloat16* __restrict__ Wh, const __nv_bfloat16* __restrict__ Wl,
    const float* __restrict__ Wb,
    const float* __restrict__ gamma, const float* __restrict__ beta,
    const float* __restrict__ mean, const float* __restrict__ var,
    const float* __restrict__ x, float* __restrict__ out)
{
    extern __shared__ char smem[];
    __nv_bfloat16* sAh = (__nv_bfloat16*)smem;
    __nv_bfloat16* sAl = sAh + 9216;
    __nv_bfloat16* sBh = sAh + 18432;
    __nv_bfloat16* sBl = sAh + 27648;
    float* sRes = (float*)smem;
    const uint32_t sbAh = smem_to_u32(sAh), sbAl = smem_to_u32(sAl);
    const uint32_t sbBh = smem_to_u32(sBh), sbBl = smem_to_u32(sBl);

    const int tid = threadIdx.x, lane = tid & 31, wid = tid >> 5;
    const int wm = wid & 3, wn = wid >> 2;
    const int b = blockIdx.z, pxt = blockIdx.y, oc0 = blockIdx.x * 128;

    float acc[2][8][4];
#pragma unroll
    for (int mt = 0; mt < 2; mt++)
#pragma unroll
        for (int nt = 0; nt < 8; nt++)
#pragma unroll
            for (int e = 0; e < 4; e++) acc[mt][nt][e] = 0.f;

    for (int ck = 0; ck < 4; ck++) {
        __syncthreads();
        {
            const __nv_bfloat16* gah = Yh + ((size_t)b * HW_ + pxt * 128) * C_ + ck * 64;
            const __nv_bfloat16* gal = Yl + ((size_t)b * HW_ + pxt * 128) * C_ + ck * 64;
            for (int idx = tid; idx < 1024; idx += 256) {
                int r = idx >> 3, u = idx & 7;
                *(uint4*)(sAh + r * 72 + u * 8) = *(const uint4*)(gah + (size_t)r * C_ + u * 8);
                *(uint4*)(sAl + r * 72 + u * 8) = *(const uint4*)(gal + (size_t)r * C_ + u * 8);
            }
            const __nv_bfloat16* gbh = Wh + (size_t)oc0 * 256 + ck * 64;
            const __nv_bfloat16* gbl = Wl + (size_t)oc0 * 256 + ck * 64;
            for (int idx = tid; idx < 1024; idx += 256) {
                int r = idx >> 3, u = idx & 7;
                *(uint4*)(sBh + r * 72 + u * 8) = *(const uint4*)(gbh + (size_t)r * 256 + u * 8);
                *(uint4*)(sBl + r * 72 + u * 8) = *(const uint4*)(gbl + (size_t)r * 256 + u * 8);
            }
        }
        __syncthreads();

#pragma unroll
        for (int ks = 0; ks < 4; ks++) {
            const int k0 = ks * 16;
            uint32_t ah[2][4], al[2][4];
            ldsm4(ah[0], a_addr(sbAh, wm * 32,      k0, lane));
            ldsm4(ah[1], a_addr(sbAh, wm * 32 + 16, k0, lane));
            ldsm4(al[0], a_addr(sbAl, wm * 32,      k0, lane));
            ldsm4(al[1], a_addr(sbAl, wm * 32 + 16, k0, lane));
#pragma unroll
            for (int g = 0; g < 4; g++) {
                uint32_t bh[4], bl[4];
                ldsm4(bh, b_addr(sbBh, wn * 64 + g * 16, k0, lane));
                ldsm4(bl, b_addr(sbBl, wn * 64 + g * 16, k0, lane));
#pragma unroll
                for (int mt = 0; mt < 2; mt++) {
                    mma16816(acc[mt][g*2],   ah[mt], bh[0], bh[1]);
                    mma16816(acc[mt][g*2],   ah[mt], bl[0], bl[1]);
                    mma16816(acc[mt][g*2],   al[mt], bh[0], bh[1]);
                    mma16816(acc[mt][g*2+1], ah[mt], bh[2], bh[3]);
                    mma16816(acc[mt][g*2+1], ah[mt], bl[2], bl[3]);
                    mma16816(acc[mt][g*2+1], al[mt], bh[2], bh[3]);
                }
            }
        }
    }

    __syncthreads();
#pragma unroll
    for (int mt = 0; mt < 2; mt++) {
        const int row = wm * 32 + mt * 16 + (lane >> 2);
#pragma unroll
        for (int nt = 0; nt < 8; nt++) {
            const int col = wn * 64 + nt * 8 + (lane & 3) * 2;
            sRes[row * 132 + col]       = acc[mt][nt][0];
            sRes[row * 132 + col + 1]   = acc[mt][nt][1];
            sRes[(row+8) * 132 + col]   = acc[mt][nt][2];
            sRes[(row+8) * 132 + col+1] = acc[mt][nt][3];
        }
    }
    __syncthreads();

    // BN + residual, write channel-major out[b][c][n]
    for (int t = tid; t < 128 * 128; t += 256) {
        int o = t >> 7, p = t & 127;
        int oc = oc0 + o;
        float scale = gamma[oc] * rsqrtf(var[oc] + EPS_);
        size_t gidx = ((size_t)b * C_ + oc) * HW_ + pxt * 128 + p;
        out[gidx] = (sRes[p * 132 + o] + Wb[oc] - mean[oc]) * scale + beta[oc] + x[gidx];
    }
}

// ======================================================================
extern "C" void kernel_launch(void* const* d_in, const int* in_sizes, int n_in,
                              void* d_out, int out_size)
{
    const float* x       = (const float*)d_in[0];
    const float* g_w     = (const float*)d_in[1];
    const float* g_b     = (const float*)d_in[2];
    const float* theta_w = (const float*)d_in[3];
    const float* theta_b = (const float*)d_in[4];
    const float* phi_w   = (const float*)d_in[5];
    const float* phi_b   = (const float*)d_in[6];
    const float* W_w     = (const float*)d_in[7];
    const float* W_b     = (const float*)d_in[8];
    const float* bn_g    = (const float*)d_in[9];
    const float* bn_b    = (const float*)d_in[10];
    const float* bn_m    = (const float*)d_in[11];
    const float* bn_v    = (const float*)d_in[12];
    float* out = (float*)d_out;

    __nv_bfloat16 *xh, *xl, *Wch, *Wcl, *Wfh, *Wfl;
    __nv_bfloat16 *Qh, *Ql, *Kh, *Kl, *Vh, *Vl, *Yh, *Yl;
    uint32_t* Pp; float *rv, *bc;
    cudaGetSymbolAddress((void**)&xh,  d_xh);
    cudaGetSymbolAddress((void**)&xl,  d_xl);
    cudaGetSymbolAddress((void**)&Wch, d_Wch);
    cudaGetSymbolAddress((void**)&Wcl, d_Wcl);
    cudaGetSymbolAddress((void**)&bc,  d_bc);
    cudaGetSymbolAddress((void**)&Wfh, d_Wfh);
    cudaGetSymbolAddress((void**)&Wfl, d_Wfl);
    cudaGetSymbolAddress((void**)&Qh,  d_Qh);
    cudaGetSymbolAddress((void**)&Ql,  d_Ql);
    cudaGetSymbolAddress((void**)&Kh,  d_Kh);
    cudaGetSymbolAddress((void**)&Kl,  d_Kl);
    cudaGetSymbolAddress((void**)&Vh,  d_Vh);
    cudaGetSymbolAddress((void**)&Vl,  d_Vl);
    cudaGetSymbolAddress((void**)&Pp,  d_Pp);
    cudaGetSymbolAddress((void**)&rv,  d_rinv);
    cudaGetSymbolAddress((void**)&Yh,  d_Yh);
    cudaGetSymbolAddress((void**)&Yl,  d_Yl);

    cudaFuncSetAttribute(conv_mma_kernel,  cudaFuncAttributeMaxDynamicSharedMemorySize, CONV_SMEM);
    cudaFuncSetAttribute(qk_mma_kernel,    cudaFuncAttributeMaxDynamicSharedMemorySize, QK_SMEM);
    cudaFuncSetAttribute(pv_mma_kernel,    cudaFuncAttributeMaxDynamicSharedMemorySize, PV_SMEM);
    cudaFuncSetAttribute(final_mma_kernel, cudaFuncAttributeMaxDynamicSharedMemorySize, FIN_SMEM);

    xsplit_kernel<<<BB * C_ * HW_ / 1024, 256>>>(x, xh, xl);
    wpack_conv_kernel<<<384, 256>>>(g_w, g_b, theta_w, theta_b, phi_w, phi_b, Wch, Wcl, bc);
    wpack_final_kernel<<<256, 256>>>(W_w, Wfh, Wfl);
    conv_mma_kernel<<<dim3(3, 32, BB), 256, CONV_SMEM>>>(xh, xl, Wch, Wcl, bc,
                                                         Vh, Vl, Qh, Ql, Kh, Kl);
    qk_mma_kernel<<<dim3(32, BB), 256, QK_SMEM>>>(Qh, Ql, Kh, Kl, Pp, rv);
    pv_mma_kernel<<<dim3(32, BB), 512, PV_SMEM>>>(Pp, Vh, Vl, rv, Yh, Yl);
    final_mma_kernel<<<dim3(2, 32, BB), 256, FIN_SMEM>>>(Yh, Yl, Wfh, Wfl, W_b,
                                                         bn_g, bn_b, bn_m, bn_v, x, out);
}

// round 7
// speedup vs baseline: 2.3189x; 1.2296x over previous
#include <cuda_runtime.h>
#include <cuda_bf16.h>
#include <cstdint>

#define BB 8
#define C_ 256
#define HW_ 4096
#define PHW_ 1024
#define EPS_ 1e-5f

// ---------------- helpers ----------------
__device__ __forceinline__ uint32_t smem_to_u32(const void* p) {
    uint32_t a;
    asm("{ .reg .u64 t; cvta.to.shared.u64 t, %1; cvt.u32.u64 %0, t; }" : "=r"(a) : "l"(p));
    return a;
}
__device__ __forceinline__ void ldsm4(uint32_t* r, uint32_t addr) {
    asm volatile("ldmatrix.sync.aligned.m8n8.x4.shared.b16 {%0,%1,%2,%3}, [%4];"
        : "=r"(r[0]), "=r"(r[1]), "=r"(r[2]), "=r"(r[3]) : "r"(addr));
}
__device__ __forceinline__ void ldsm4t(uint32_t* r, uint32_t addr) {
    asm volatile("ldmatrix.sync.aligned.m8n8.x4.trans.shared.b16 {%0,%1,%2,%3}, [%4];"
        : "=r"(r[0]), "=r"(r[1]), "=r"(r[2]), "=r"(r[3]) : "r"(addr));
}
__device__ __forceinline__ void mma16816(float* d, const uint32_t* a, uint32_t b0, uint32_t b1) {
    asm volatile("mma.sync.aligned.m16n8k16.row.col.f32.bf16.bf16.f32 "
        "{%0,%1,%2,%3}, {%4,%5,%6,%7}, {%8,%9}, {%0,%1,%2,%3};"
        : "+f"(d[0]), "+f"(d[1]), "+f"(d[2]), "+f"(d[3])
        : "r"(a[0]), "r"(a[1]), "r"(a[2]), "r"(a[3]), "r"(b0), "r"(b1));
}
__device__ __forceinline__ void cp16(uint32_t s, const void* g) {
    asm volatile("cp.async.cg.shared.global [%0], [%1], 16;" :: "r"(s), "l"(g));
}
#define CP_COMMIT() asm volatile("cp.async.commit_group;" ::: "memory")
#define CP_WAIT0()  asm volatile("cp.async.wait_group 0;" ::: "memory")
#define CP_WAIT1()  asm volatile("cp.async.wait_group 1;" ::: "memory")

__device__ __forceinline__ void split_bf16(float v, __nv_bfloat16& h, __nv_bfloat16& l) {
    h = __float2bfloat16(v);
    l = __float2bfloat16(v - __bfloat162float(h));
}
__device__ __forceinline__ void split2(float a, float b, uint32_t& hh, uint32_t& ll) {
    __nv_bfloat16 ha, la, hb, lb;
    split_bf16(a, ha, la); split_bf16(b, hb, lb);
    hh = (uint32_t)__bfloat16_as_ushort(ha) | ((uint32_t)__bfloat16_as_ushort(hb) << 16);
    ll = (uint32_t)__bfloat16_as_ushort(la) | ((uint32_t)__bfloat16_as_ushort(lb) << 16);
}

// A-fragment (m16k16) from [m][k] row-major smem, pitch 72
__device__ __forceinline__ uint32_t a_addr(uint32_t base, int row0, int k0, int lane) {
    int r = row0 + (lane & 15), c = k0 + ((lane >> 4) << 3);
    return base + (uint32_t)((r * 72 + c) * 2);
}
// A-fragment (m16k16) from [k][m] storage via trans-ldmatrix, pitch P
__device__ __forceinline__ uint32_t at_addr(uint32_t base, int m0, int k0, int lane, int P) {
    int t = lane >> 3;
    int m = m0 + ((t & 1) << 3);
    int k = k0 + ((t >> 1) << 3) + (lane & 7);
    return base + (uint32_t)((k * P + m) * 2);
}
// B-fragment x4 (two n8k16 tiles) from [n][k] row-major smem, pitch 72
__device__ __forceinline__ uint32_t b_addr(uint32_t base, int n0, int k0, int lane) {
    int r = n0 + (lane & 7) + ((lane >> 4) << 3), c = k0 + (((lane >> 3) & 1) << 3);
    return base + (uint32_t)((r * 72 + c) * 2);
}

// ---------------- scratch ----------------
__device__ __nv_bfloat16 d_xh[BB*C_*HW_], d_xl[BB*C_*HW_];
__device__ __nv_bfloat16 d_Wch[384*256],  d_Wcl[384*256];
__device__ float         d_bc[384];
__device__ __nv_bfloat16 d_Wfh[256*256],  d_Wfl[256*256];
__device__ __nv_bfloat16 d_Qh[BB*HW_*64],  d_Ql[BB*HW_*64];
__device__ __nv_bfloat16 d_Kh[BB*PHW_*64], d_Kl[BB*PHW_*64];
__device__ __nv_bfloat16 d_Vh[BB*C_*PHW_], d_Vl[BB*C_*PHW_];
__device__ __nv_bfloat16 d_Ph[(size_t)BB*HW_*PHW_], d_Pl[(size_t)BB*HW_*PHW_];
__device__ float         d_rinv[BB*HW_];
__device__ __nv_bfloat16 d_Yh[BB*HW_*C_],  d_Yl[BB*HW_*C_];

// ======================================================================
// xsplit + weight packing
// ======================================================================
__global__ __launch_bounds__(256) void xsplit_kernel(
    const float* __restrict__ x, __nv_bfloat16* __restrict__ xh, __nv_bfloat16* __restrict__ xl)
{
    size_t i = ((size_t)blockIdx.x * 256 + threadIdx.x) * 4;
    float4 v = *(const float4*)(x + i);
    uint32_t h0, l0, h1, l1;
    split2(v.x, v.y, h0, l0);
    split2(v.z, v.w, h1, l1);
    *(uint2*)(xh + i) = make_uint2(h0, h1);
    *(uint2*)(xl + i) = make_uint2(l0, l1);
}

__global__ void wpack_conv_kernel(
    const float* __restrict__ g_w, const float* __restrict__ g_b,
    const float* __restrict__ th_w, const float* __restrict__ th_b,
    const float* __restrict__ ph_w, const float* __restrict__ ph_b,
    __nv_bfloat16* __restrict__ Wh, __nv_bfloat16* __restrict__ Wl, float* __restrict__ bc)
{
    int oc = blockIdx.x, k = threadIdx.x;
    float v;
    if (oc < 256)       v = g_w[oc * 256 + k];
    else if (oc < 320)  v = (k < 64) ? th_w[(oc - 256) * 64 + k] : 0.f;
    else                v = (k >= 64) ? ph_w[(oc - 320) * 192 + (k - 64)] : 0.f;
    __nv_bfloat16 h, l; split_bf16(v, h, l);
    Wh[oc * 256 + k] = h; Wl[oc * 256 + k] = l;
    if (k == 0)
        bc[oc] = (oc < 256) ? g_b[oc] : (oc < 320) ? th_b[oc - 256] : ph_b[oc - 320];
}

__global__ void wpack_final_kernel(const float* __restrict__ w,
    __nv_bfloat16* __restrict__ Wh, __nv_bfloat16* __restrict__ Wl)
{
    int i = blockIdx.x * 256 + threadIdx.x;
    __nv_bfloat16 h, l; split_bf16(w[i], h, l);
    Wh[i] = h; Wl[i] = l;
}

// ======================================================================
// conv_mma: grid (3, 32, 8), block 256; cp.async 2-stage.
// stage s @ s*71680: Xh[64][136] Xl(+17408) Wh[128][72](+34816) Wl(+53248)
// epilogue fp32 [128][132] union at 0
// ======================================================================
static constexpr int CONV_STG = 71680;
static constexpr int CONV_SMEM = 2 * CONV_STG;

__global__ __launch_bounds__(256) void conv_mma_kernel(
    const __nv_bfloat16* __restrict__ xh, const __nv_bfloat16* __restrict__ xl,
    const __nv_bfloat16* __restrict__ Wh, const __nv_bfloat16* __restrict__ Wl,
    const float* __restrict__ bc,
    __nv_bfloat16* __restrict__ Vh, __nv_bfloat16* __restrict__ Vl,
    __nv_bfloat16* __restrict__ Qh, __nv_bfloat16* __restrict__ Ql,
    __nv_bfloat16* __restrict__ Kh, __nv_bfloat16* __restrict__ Kl)
{
    extern __shared__ char smem[];
    const uint32_t sb = smem_to_u32(smem);
    float* sRes = (float*)smem;
    const int tid = threadIdx.x, lane = tid & 31, wid = tid >> 5;
    const int wm = wid & 3, wn = wid >> 2;
    const int b = blockIdx.z, pxt = blockIdx.y, oc0 = blockIdx.x * 128;

    auto prefetch = [&](int c) {
        uint32_t base = sb + (c & 1) * CONV_STG;
        const __nv_bfloat16* gxh = xh + ((size_t)b * C_ + c * 64) * HW_ + pxt * 128;
        const __nv_bfloat16* gxl = xl + ((size_t)b * C_ + c * 64) * HW_ + pxt * 128;
        for (int idx = tid; idx < 1024; idx += 256) {
            int r = idx >> 4, u = idx & 15;
            uint32_t so = (uint32_t)((r * 136 + u * 8) * 2);
            cp16(base + so,         gxh + (size_t)r * HW_ + u * 8);
            cp16(base + 17408 + so, gxl + (size_t)r * HW_ + u * 8);
        }
        const __nv_bfloat16* gwh = Wh + (size_t)oc0 * 256 + c * 64;
        const __nv_bfloat16* gwl = Wl + (size_t)oc0 * 256 + c * 64;
        for (int idx = tid; idx < 1024; idx += 256) {
            int r = idx >> 3, u = idx & 7;
            uint32_t so = (uint32_t)((r * 72 + u * 8) * 2);
            cp16(base + 34816 + so, gwh + (size_t)r * 256 + u * 8);
            cp16(base + 53248 + so, gwl + (size_t)r * 256 + u * 8);
        }
        CP_COMMIT();
    };

    float acc[2][8][4];
#pragma unroll
    for (int mt = 0; mt < 2; mt++)
#pragma unroll
        for (int nt = 0; nt < 8; nt++)
#pragma unroll
            for (int e = 0; e < 4; e++) acc[mt][nt][e] = 0.f;

    prefetch(0);
    for (int ck = 0; ck < 4; ck++) {
        if (ck + 1 < 4) { prefetch(ck + 1); CP_WAIT1(); } else CP_WAIT0();
        __syncthreads();
        uint32_t base = sb + (ck & 1) * CONV_STG;
#pragma unroll
        for (int ks = 0; ks < 4; ks++) {
            const int k0 = ks * 16;
            uint32_t ah[2][4], al[2][4];
            ldsm4t(ah[0], at_addr(base,         wm * 32,      k0, lane, 136));
            ldsm4t(ah[1], at_addr(base,         wm * 32 + 16, k0, lane, 136));
            ldsm4t(al[0], at_addr(base + 17408, wm * 32,      k0, lane, 136));
            ldsm4t(al[1], at_addr(base + 17408, wm * 32 + 16, k0, lane, 136));
#pragma unroll
            for (int g = 0; g < 4; g++) {
                uint32_t bh[4], bl[4];
                ldsm4(bh, b_addr(base + 34816, wn * 64 + g * 16, k0, lane));
                ldsm4(bl, b_addr(base + 53248, wn * 64 + g * 16, k0, lane));
#pragma unroll
                for (int mt = 0; mt < 2; mt++) {
                    mma16816(acc[mt][g*2],   ah[mt], bh[0], bh[1]);
                    mma16816(acc[mt][g*2],   ah[mt], bl[0], bl[1]);
                    mma16816(acc[mt][g*2],   al[mt], bh[0], bh[1]);
                    mma16816(acc[mt][g*2+1], ah[mt], bh[2], bh[3]);
                    mma16816(acc[mt][g*2+1], ah[mt], bl[2], bl[3]);
                    mma16816(acc[mt][g*2+1], al[mt], bh[2], bh[3]);
                }
            }
        }
        __syncthreads();
    }

#pragma unroll
    for (int mt = 0; mt < 2; mt++) {
        const int row = wm * 32 + mt * 16 + (lane >> 2);
#pragma unroll
        for (int nt = 0; nt < 8; nt++) {
            const int col = wn * 64 + nt * 8 + (lane & 3) * 2;
            sRes[row * 132 + col]       = acc[mt][nt][0];
            sRes[row * 132 + col + 1]   = acc[mt][nt][1];
            sRes[(row+8) * 132 + col]   = acc[mt][nt][2];
            sRes[(row+8) * 132 + col+1] = acc[mt][nt][3];
        }
    }
    __syncthreads();

    if (oc0 < 256) {
        for (int t = tid; t < 32 * 128; t += 256) {
            int pw = t >> 7, lo = t & 127, oc = oc0 + lo;
            float v = fmaxf(fmaxf(sRes[(2*pw)*132 + lo], sRes[(2*pw+1)*132 + lo]),
                            fmaxf(sRes[(64+2*pw)*132 + lo], sRes[(65+2*pw)*132 + lo]))
                      + bc[oc];
            __nv_bfloat16 h, l; split_bf16(v, h, l);
            size_t oidx = ((size_t)b * C_ + oc) * PHW_ + pxt * 32 + pw;
            Vh[oidx] = h; Vl[oidx] = l;
        }
    } else {
        for (int t = tid; t < 128 * 64; t += 256) {
            int p = t >> 6, o = t & 63;
            float v = sRes[p * 132 + o] + bc[256 + o];
            __nv_bfloat16 h, l; split_bf16(v, h, l);
            size_t oidx = ((size_t)b * HW_ + pxt * 128 + p) * 64 + o;
            Qh[oidx] = h; Ql[oidx] = l;
        }
        for (int t = tid; t < 32 * 64; t += 256) {
            int pw = t >> 6, o = t & 63, lo = 64 + o;
            float v = fmaxf(fmaxf(sRes[(2*pw)*132 + lo], sRes[(2*pw+1)*132 + lo]),
                            fmaxf(sRes[(64+2*pw)*132 + lo], sRes[(65+2*pw)*132 + lo]))
                      + bc[320 + o];
            __nv_bfloat16 h, l; split_bf16(v, h, l);
            size_t oidx = ((size_t)b * PHW_ + pxt * 32 + pw) * 64 + o;
            Kh[oidx] = h; Kl[oidx] = l;
        }
    }
}

// ======================================================================
// qk_mma: S = Q K^T + fused exp/rowsum. grid (32, 8), block 256.
// smem: Qh@0 Ql@18432; K stage s @ 36864 + s*36864 (hi@0, lo@18432); rs@110592
// ======================================================================
static constexpr int QK_SMEM = 110592 + 1024;

__global__ __launch_bounds__(256) void qk_mma_kernel(
    const __nv_bfloat16* __restrict__ Qh, const __nv_bfloat16* __restrict__ Ql,
    const __nv_bfloat16* __restrict__ Kh, const __nv_bfloat16* __restrict__ Kl,
    __nv_bfloat16* __restrict__ Ph, __nv_bfloat16* __restrict__ Pl,
    float* __restrict__ rinv)
{
    extern __shared__ char smem[];
    const uint32_t sb = smem_to_u32(smem);
    __nv_bfloat16* sQ = (__nv_bfloat16*)smem;
    float* rs = (float*)(smem + 110592);
    const int tid = threadIdx.x, lane = tid & 31, wid = tid >> 5;
    const int wm = wid & 3, wn = wid >> 2;
    const int b = blockIdx.y, n0 = blockIdx.x * 128;

    auto prefetch = [&](int c) {
        uint32_t base = sb + 36864 + (c & 1) * 36864;
        const __nv_bfloat16* gkh = Kh + ((size_t)b * PHW_ + c * 128) * 64;
        const __nv_bfloat16* gkl = Kl + ((size_t)b * PHW_ + c * 128) * 64;
        for (int idx = tid; idx < 1024; idx += 256) {
            int r = idx >> 3, u = idx & 7;
            uint32_t so = (uint32_t)((r * 72 + u * 8) * 2);
            cp16(base + so,         gkh + r * 64 + u * 8);
            cp16(base + 18432 + so, gkl + r * 64 + u * 8);
        }
        CP_COMMIT();
    };

    prefetch(0);
    {   // resident Q tile (plain loads overlap prefetch 0)
        const __nv_bfloat16* gqh = Qh + ((size_t)b * HW_ + n0) * 64;
        const __nv_bfloat16* gql = Ql + ((size_t)b * HW_ + n0) * 64;
        for (int idx = tid; idx < 1024; idx += 256) {
            int r = idx >> 3, u = idx & 7;
            *(uint4*)(sQ + r * 72 + u * 8)        = *(const uint4*)(gqh + r * 64 + u * 8);
            *(uint4*)(sQ + 9216 + r * 72 + u * 8) = *(const uint4*)(gql + r * 64 + u * 8);
        }
    }

    float rsum[2][2] = {{0.f, 0.f}, {0.f, 0.f}};

    for (int ck = 0; ck < 8; ck++) {
        const int m0 = ck * 128;
        if (ck + 1 < 8) { prefetch(ck + 1); CP_WAIT1(); } else CP_WAIT0();
        __syncthreads();
        uint32_t kb = sb + 36864 + (ck & 1) * 36864;

        float acc[2][8][4];
#pragma unroll
        for (int mt = 0; mt < 2; mt++)
#pragma unroll
            for (int nt = 0; nt < 8; nt++)
#pragma unroll
                for (int e = 0; e < 4; e++) acc[mt][nt][e] = 0.f;

#pragma unroll
        for (int ks = 0; ks < 4; ks++) {
            const int k0 = ks * 16;
            uint32_t ah[2][4], al[2][4];
            ldsm4(ah[0], a_addr(sb,         wm * 32,      k0, lane));
            ldsm4(ah[1], a_addr(sb,         wm * 32 + 16, k0, lane));
            ldsm4(al[0], a_addr(sb + 18432, wm * 32,      k0, lane));
            ldsm4(al[1], a_addr(sb + 18432, wm * 32 + 16, k0, lane));
#pragma unroll
            for (int g = 0; g < 4; g++) {
                uint32_t bh[4], bl[4];
                ldsm4(bh, b_addr(kb,         wn * 64 + g * 16, k0, lane));
                ldsm4(bl, b_addr(kb + 18432, wn * 64 + g * 16, k0, lane));
#pragma unroll
                for (int mt = 0; mt < 2; mt++) {
                    mma16816(acc[mt][g*2],   ah[mt], bh[0], bh[1]);
                    mma16816(acc[mt][g*2],   ah[mt], bl[0], bl[1]);
                    mma16816(acc[mt][g*2],   al[mt], bh[0], bh[1]);
                    mma16816(acc[mt][g*2+1], ah[mt], bh[2], bh[3]);
                    mma16816(acc[mt][g*2+1], ah[mt], bl[2], bl[3]);
                    mma16816(acc[mt][g*2+1], al[mt], bh[2], bh[3]);
                }
            }
        }

#pragma unroll
        for (int mt = 0; mt < 2; mt++) {
            const int row = n0 + wm * 32 + mt * 16 + (lane >> 2);
#pragma unroll
            for (int nt = 0; nt < 8; nt++) {
                float e0 = __expf(acc[mt][nt][0]);
                float e1 = __expf(acc[mt][nt][1]);
                float e2 = __expf(acc[mt][nt][2]);
                float e3 = __expf(acc[mt][nt][3]);
                rsum[mt][0] += e0 + e1;
                rsum[mt][1] += e2 + e3;
                const int col = m0 + wn * 64 + nt * 8 + (lane & 3) * 2;
                uint32_t hh, ll;
                split2(e0, e1, hh, ll);
                *(uint32_t*)&Ph[((size_t)b * HW_ + row) * PHW_ + col] = hh;
                *(uint32_t*)&Pl[((size_t)b * HW_ + row) * PHW_ + col] = ll;
                split2(e2, e3, hh, ll);
                *(uint32_t*)&Ph[((size_t)b * HW_ + row + 8) * PHW_ + col] = hh;
                *(uint32_t*)&Pl[((size_t)b * HW_ + row + 8) * PHW_ + col] = ll;
            }
        }
        __syncthreads();
    }

#pragma unroll
    for (int mt = 0; mt < 2; mt++)
#pragma unroll
        for (int hh = 0; hh < 2; hh++) {
            float s = rsum[mt][hh];
            s += __shfl_xor_sync(0xffffffffu, s, 1);
            s += __shfl_xor_sync(0xffffffffu, s, 2);
            if ((lane & 3) == 0)
                rs[wn * 128 + wm * 32 + mt * 16 + hh * 8 + (lane >> 2)] = s;
        }
    __syncthreads();
    if (tid < 128)
        rinv[(size_t)b * HW_ + n0 + tid] = 1.f / (rs[tid] + rs[128 + tid]);
}

// ======================================================================
// pv_mma: Y = exp(S) @ V * rinv. grid (32, 8), block 512; cp.async 2-stage.
// stage s @ s*110592: Ah[128][72] Al(+18432) Bh[256][72](+36864) Bl(+73728)
// ======================================================================
static constexpr int PV_STG = 110592;
static constexpr int PV_SMEM = 2 * PV_STG;

__global__ __launch_bounds__(512) void pv_mma_kernel(
    const __nv_bfloat16* __restrict__ Ph, const __nv_bfloat16* __restrict__ Pl,
    const __nv_bfloat16* __restrict__ Vh, const __nv_bfloat16* __restrict__ Vl,
    const float* __restrict__ rinv,
    __nv_bfloat16* __restrict__ Yh, __nv_bfloat16* __restrict__ Yl)
{
    extern __shared__ char smem[];
    const uint32_t sb = smem_to_u32(smem);
    const int tid = threadIdx.x, lane = tid & 31, wid = tid >> 5;
    const int wm = wid & 3, wn = wid >> 2;
    const int b = blockIdx.y, n0 = blockIdx.x * 128;

    auto prefetch = [&](int c) {
        uint32_t base = sb + (c & 1) * PV_STG;
        const __nv_bfloat16* gph = Ph + ((size_t)b * HW_ + n0) * PHW_ + c * 64;
        const __nv_bfloat16* gpl = Pl + ((size_t)b * HW_ + n0) * PHW_ + c * 64;
        for (int idx = tid; idx < 1024; idx += 512) {
            int r = idx >> 3, u = idx & 7;
            uint32_t so = (uint32_t)((r * 72 + u * 8) * 2);
            cp16(base + so,         gph + (size_t)r * PHW_ + u * 8);
            cp16(base + 18432 + so, gpl + (size_t)r * PHW_ + u * 8);
        }
        const __nv_bfloat16* gvh = Vh + (size_t)b * C_ * PHW_ + c * 64;
        const __nv_bfloat16* gvl = Vl + (size_t)b * C_ * PHW_ + c * 64;
        for (int idx = tid; idx < 2048; idx += 512) {
            int r = idx >> 3, u = idx & 7;
            uint32_t so = (uint32_t)((r * 72 + u * 8) * 2);
            cp16(base + 36864 + so, gvh + (size_t)r * PHW_ + u * 8);
            cp16(base + 73728 + so, gvl + (size_t)r * PHW_ + u * 8);
        }
        CP_COMMIT();
    };

    float acc[2][8][4];
#pragma unroll
    for (int mt = 0; mt < 2; mt++)
#pragma unroll
        for (int nt = 0; nt < 8; nt++)
#pragma unroll
            for (int e = 0; e < 4; e++) acc[mt][nt][e] = 0.f;

    prefetch(0);
    for (int ck = 0; ck < 16; ck++) {
        if (ck + 1 < 16) { prefetch(ck + 1); CP_WAIT1(); } else CP_WAIT0();
        __syncthreads();
        uint32_t base = sb + (ck & 1) * PV_STG;
#pragma unroll
        for (int ks = 0; ks < 4; ks++) {
            const int k0 = ks * 16;
            uint32_t ah[2][4], al[2][4];
            ldsm4(ah[0], a_addr(base,         wm * 32,      k0, lane));
            ldsm4(ah[1], a_addr(base,         wm * 32 + 16, k0, lane));
            ldsm4(al[0], a_addr(base + 18432, wm * 32,      k0, lane));
            ldsm4(al[1], a_addr(base + 18432, wm * 32 + 16, k0, lane));
#pragma unroll
            for (int g = 0; g < 4; g++) {
                uint32_t bh[4], bl[4];
                ldsm4(bh, b_addr(base + 36864, wn * 64 + g * 16, k0, lane));
                ldsm4(bl, b_addr(base + 73728, wn * 64 + g * 16, k0, lane));
#pragma unroll
                for (int mt = 0; mt < 2; mt++) {
                    mma16816(acc[mt][g*2],   ah[mt], bh[0], bh[1]);
                    mma16816(acc[mt][g*2],   ah[mt], bl[0], bl[1]);
                    mma16816(acc[mt][g*2],   al[mt], bh[0], bh[1]);
                    mma16816(acc[mt][g*2+1], ah[mt], bh[2], bh[3]);
                    mma16816(acc[mt][g*2+1], ah[mt], bl[2], bl[3]);
                    mma16816(acc[mt][g*2+1], al[mt], bh[2], bh[3]);
                }
            }
        }
        __syncthreads();
    }

#pragma unroll
    for (int mt = 0; mt < 2; mt++) {
        const int r0 = n0 + wm * 32 + mt * 16 + (lane >> 2);
        const float i0 = rinv[(size_t)b * HW_ + r0];
        const float i1 = rinv[(size_t)b * HW_ + r0 + 8];
#pragma unroll
        for (int nt = 0; nt < 8; nt++) {
            const int col = wn * 64 + nt * 8 + (lane & 3) * 2;
            uint32_t hh, ll;
            split2(acc[mt][nt][0] * i0, acc[mt][nt][1] * i0, hh, ll);
            *(uint32_t*)&Yh[((size_t)b * HW_ + r0) * C_ + col] = hh;
            *(uint32_t*)&Yl[((size_t)b * HW_ + r0) * C_ + col] = ll;
            split2(acc[mt][nt][2] * i1, acc[mt][nt][3] * i1, hh, ll);
            *(uint32_t*)&Yh[((size_t)b * HW_ + r0 + 8) * C_ + col] = hh;
            *(uint32_t*)&Yl[((size_t)b * HW_ + r0 + 8) * C_ + col] = ll;
        }
    }
}

// ======================================================================
// final_mma: out = BN(Y @ W^T + Wb) + x. grid (2, 32, 8), block 256; 2-stage.
// stage s @ s*73728: Ah[128][72] Al(+18432) Bh[128][72](+36864) Bl(+55296)
// epilogue fp32 [128][132] union at 0
// ======================================================================
static constexpr int FIN_STG = 73728;
static constexpr int FIN_SMEM = 2 * FIN_STG;

__global__ __launch_bounds__(256) void final_mma_kernel(
    const __nv_bfloat16* __restrict__ Yh, const __nv_bfloat16* __restrict__ Yl,
    const __nv_bfloat16* __restrict__ Wh, const __nv_bfloat16* __restrict__ Wl,
    const float* __restrict__ Wb,
    const float* __restrict__ gamma, const float* __restrict__ beta,
    const float* __restrict__ mean, const float* __restrict__ var,
    const float* __restrict__ x, float* __restrict__ out)
{
    extern __shared__ char smem[];
    const uint32_t sb = smem_to_u32(smem);
    float* sRes = (float*)smem;
    const int tid = threadIdx.x, lane = tid & 31, wid = tid >> 5;
    const int wm = wid & 3, wn = wid >> 2;
    const int b = blockIdx.z, pxt = blockIdx.y, oc0 = blockIdx.x * 128;

    auto prefetch = [&](int c) {
        uint32_t base = sb + (c & 1) * FIN_STG;
        const __nv_bfloat16* gah = Yh + ((size_t)b * HW_ + pxt * 128) * C_ + c * 64;
        const __nv_bfloat16* gal = Yl + ((size_t)b * HW_ + pxt * 128) * C_ + c * 64;
        for (int idx = tid; idx < 1024; idx += 256) {
            int r = idx >> 3, u = idx & 7;
            uint32_t so = (uint32_t)((r * 72 + u * 8) * 2);
            cp16(base + so,         gah + (size_t)r * C_ + u * 8);
            cp16(base + 18432 + so, gal + (size_t)r * C_ + u * 8);
        }
        const __nv_bfloat16* gbh = Wh + (size_t)oc0 * 256 + c * 64;
        const __nv_bfloat16* gbl = Wl + (size_t)oc0 * 256 + c * 64;
        for (int idx = tid; idx < 1024; idx += 256) {
            int r = idx >> 3, u = idx & 7;
            uint32_t so = (uint32_t)((r * 72 + u * 8) * 2);
            cp16(base + 36864 + so, gbh + (size_t)r * 256 + u * 8);
            cp16(base + 55296 + so, gbl + (size_t)r * 256 + u * 8);
        }
        CP_COMMIT();
    };

    float acc[2][8][4];
#pragma unroll
    for (int mt = 0; mt < 2; mt++)
#pragma unroll
        for (int nt = 0; nt < 8; nt++)
#pragma unroll
            for (int e = 0; e < 4; e++) acc[mt][nt][e] = 0.f;

    prefetch(0);
    for (int ck = 0; ck < 4; ck++) {
        if (ck + 1 < 4) { prefetch(ck + 1); CP_WAIT1(); } else CP_WAIT0();
        __syncthreads();
        uint32_t base = sb + (ck & 1) * FIN_STG;
#pragma unroll
        for (int ks = 0; ks < 4; ks++) {
            const int k0 = ks * 16;
            uint32_t ah[2][4], al[2][4];
            ldsm4(ah[0], a_addr(base,         wm * 32,      k0, lane));
            ldsm4(ah[1], a_addr(base,         wm * 32 + 16, k0, lane));
            ldsm4(al[0], a_addr(base + 18432, wm * 32,      k0, lane));
            ldsm4(al[1], a_addr(base + 18432, wm * 32 + 16, k0, lane));
#pragma unroll
            for (int g = 0; g < 4; g++) {
                uint32_t bh[4], bl[4];
                ldsm4(bh, b_addr(base + 36864, wn * 64 + g * 16, k0, lane));
                ldsm4(bl, b_addr(base + 55296, wn * 64 + g * 16, k0, lane));
#pragma unroll
                for (int mt = 0; mt < 2; mt++) {
                    mma16816(acc[mt][g*2],   ah[mt], bh[0], bh[1]);
                    mma16816(acc[mt][g*2],   ah[mt], bl[0], bl[1]);
                    mma16816(acc[mt][g*2],   al[mt], bh[0], bh[1]);
                    mma16816(acc[mt][g*2+1], ah[mt], bh[2], bh[3]);
                    mma16816(acc[mt][g*2+1], ah[mt], bl[2], bl[3]);
                    mma16816(acc[mt][g*2+1], al[mt], bh[2], bh[3]);
                }
            }
        }
        __syncthreads();
    }

#pragma unroll
    for (int mt = 0; mt < 2; mt++) {
        const int row = wm * 32 + mt * 16 + (lane >> 2);
#pragma unroll
        for (int nt = 0; nt < 8; nt++) {
            const int col = wn * 64 + nt * 8 + (lane & 3) * 2;
            sRes[row * 132 + col]       = acc[mt][nt][0];
            sRes[row * 132 + col + 1]   = acc[mt][nt][1];
            sRes[(row+8) * 132 + col]   = acc[mt][nt][2];
            sRes[(row+8) * 132 + col+1] = acc[mt][nt][3];
        }
    }
    __syncthreads();

    for (int t = tid; t < 128 * 128; t += 256) {
        int o = t >> 7, p = t & 127;
        int oc = oc0 + o;
        float scale = gamma[oc] * rsqrtf(var[oc] + EPS_);
        size_t gidx = ((size_t)b * C_ + oc) * HW_ + pxt * 128 + p;
        out[gidx] = (sRes[p * 132 + o] + Wb[oc] - mean[oc]) * scale + beta[oc] + x[gidx];
    }
}

// ======================================================================
extern "C" void kernel_launch(void* const* d_in, const int* in_sizes, int n_in,
                              void* d_out, int out_size)
{
    const float* x       = (const float*)d_in[0];
    const float* g_w     = (const float*)d_in[1];
    const float* g_b     = (const float*)d_in[2];
    const float* theta_w = (const float*)d_in[3];
    const float* theta_b = (const float*)d_in[4];
    const float* phi_w   = (const float*)d_in[5];
    const float* phi_b   = (const float*)d_in[6];
    const float* W_w     = (const float*)d_in[7];
    const float* W_b     = (const float*)d_in[8];
    const float* bn_g    = (const float*)d_in[9];
    const float* bn_b    = (const float*)d_in[10];
    const float* bn_m    = (const float*)d_in[11];
    const float* bn_v    = (const float*)d_in[12];
    float* out = (float*)d_out;

    __nv_bfloat16 *xh, *xl, *Wch, *Wcl, *Wfh, *Wfl;
    __nv_bfloat16 *Qh, *Ql, *Kh, *Kl, *Vh, *Vl, *Ph, *Pl, *Yh, *Yl;
    float *rv, *bc;
    cudaGetSymbolAddress((void**)&xh,  d_xh);
    cudaGetSymbolAddress((void**)&xl,  d_xl);
    cudaGetSymbolAddress((void**)&Wch, d_Wch);
    cudaGetSymbolAddress((void**)&Wcl, d_Wcl);
    cudaGetSymbolAddress((void**)&bc,  d_bc);
    cudaGetSymbolAddress((void**)&Wfh, d_Wfh);
    cudaGetSymbolAddress((void**)&Wfl, d_Wfl);
    cudaGetSymbolAddress((void**)&Qh,  d_Qh);
    cudaGetSymbolAddress((void**)&Ql,  d_Ql);
    cudaGetSymbolAddress((void**)&Kh,  d_Kh);
    cudaGetSymbolAddress((void**)&Kl,  d_Kl);
    cudaGetSymbolAddress((void**)&Vh,  d_Vh);
    cudaGetSymbolAddress((void**)&Vl,  d_Vl);
    cudaGetSymbolAddress((void**)&Ph,  d_Ph);
    cudaGetSymbolAddress((void**)&Pl,  d_Pl);
    cudaGetSymbolAddress((void**)&rv,  d_rinv);
    cudaGetSymbolAddress((void**)&Yh,  d_Yh);
    cudaGetSymbolAddress((void**)&Yl,  d_Yl);

    cudaFuncSetAttribute(conv_mma_kernel,  cudaFuncAttributeMaxDynamicSharedMemorySize, CONV_SMEM);
    cudaFuncSetAttribute(qk_mma_kernel,    cudaFuncAttributeMaxDynamicSharedMemorySize, QK_SMEM);
    cudaFuncSetAttribute(pv_mma_kernel,    cudaFuncAttributeMaxDynamicSharedMemorySize, PV_SMEM);
    cudaFuncSetAttribute(final_mma_kernel, cudaFuncAttributeMaxDynamicSharedMemorySize, FIN_SMEM);

    xsplit_kernel<<<BB * C_ * HW_ / 1024, 256>>>(x, xh, xl);
    wpack_conv_kernel<<<384, 256>>>(g_w, g_b, theta_w, theta_b, phi_w, phi_b, Wch, Wcl, bc);
    wpack_final_kernel<<<256, 256>>>(W_w, Wfh, Wfl);
    conv_mma_kernel<<<dim3(3, 32, BB), 256, CONV_SMEM>>>(xh, xl, Wch, Wcl, bc,
                                                         Vh, Vl, Qh, Ql, Kh, Kl);
    qk_mma_kernel<<<dim3(32, BB), 256, QK_SMEM>>>(Qh, Ql, Kh, Kl, Ph, Pl, rv);
    pv_mma_kernel<<<dim3(32, BB), 512, PV_SMEM>>>(Ph, Pl, Vh, Vl, rv, Yh, Yl);
    final_mma_kernel<<<dim3(2, 32, BB), 256, FIN_SMEM>>>(Yh, Yl, Wfh, Wfl, W_b,
                                                         bn_g, bn_b, bn_m, bn_v, x, out);
}

// round 8
// speedup vs baseline: 2.4225x; 1.0446x over previous
#include <cuda_runtime.h>
#include <cuda_bf16.h>
#include <cstdint>

#define BB 8
#define C_ 256
#define HW_ 4096
#define PHW_ 1024
#define EPS_ 1e-5f

// ---------------- helpers ----------------
__device__ __forceinline__ uint32_t smem_to_u32(const void* p) {
    uint32_t a;
    asm("{ .reg .u64 t; cvta.to.shared.u64 t, %1; cvt.u32.u64 %0, t; }" : "=r"(a) : "l"(p));
    return a;
}
__device__ __forceinline__ void ldsm4(uint32_t* r, uint32_t addr) {
    asm volatile("ldmatrix.sync.aligned.m8n8.x4.shared.b16 {%0,%1,%2,%3}, [%4];"
        : "=r"(r[0]), "=r"(r[1]), "=r"(r[2]), "=r"(r[3]) : "r"(addr));
}
__device__ __forceinline__ void ldsm4t(uint32_t* r, uint32_t addr) {
    asm volatile("ldmatrix.sync.aligned.m8n8.x4.trans.shared.b16 {%0,%1,%2,%3}, [%4];"
        : "=r"(r[0]), "=r"(r[1]), "=r"(r[2]), "=r"(r[3]) : "r"(addr));
}
__device__ __forceinline__ void mma16816(float* d, const uint32_t* a, uint32_t b0, uint32_t b1) {
    asm volatile("mma.sync.aligned.m16n8k16.row.col.f32.bf16.bf16.f32 "
        "{%0,%1,%2,%3}, {%4,%5,%6,%7}, {%8,%9}, {%0,%1,%2,%3};"
        : "+f"(d[0]), "+f"(d[1]), "+f"(d[2]), "+f"(d[3])
        : "r"(a[0]), "r"(a[1]), "r"(a[2]), "r"(a[3]), "r"(b0), "r"(b1));
}
__device__ __forceinline__ void cp16(uint32_t s, const void* g) {
    asm volatile("cp.async.cg.shared.global [%0], [%1], 16;" :: "r"(s), "l"(g));
}
#define CP_COMMIT() asm volatile("cp.async.commit_group;" ::: "memory")
#define CP_WAIT0()  asm volatile("cp.async.wait_group 0;" ::: "memory")
#define CP_WAIT1()  asm volatile("cp.async.wait_group 1;" ::: "memory")

__device__ __forceinline__ void split_bf16(float v, __nv_bfloat16& h, __nv_bfloat16& l) {
    h = __float2bfloat16(v);
    l = __float2bfloat16(v - __bfloat162float(h));
}
__device__ __forceinline__ void split2(float a, float b, uint32_t& hh, uint32_t& ll) {
    __nv_bfloat16 ha, la, hb, lb;
    split_bf16(a, ha, la); split_bf16(b, hb, lb);
    hh = (uint32_t)__bfloat16_as_ushort(ha) | ((uint32_t)__bfloat16_as_ushort(hb) << 16);
    ll = (uint32_t)__bfloat16_as_ushort(la) | ((uint32_t)__bfloat16_as_ushort(lb) << 16);
}

// A-fragment (m16k16) from [m][k] row-major smem, pitch 72
__device__ __forceinline__ uint32_t a_addr(uint32_t base, int row0, int k0, int lane) {
    int r = row0 + (lane & 15), c = k0 + ((lane >> 4) << 3);
    return base + (uint32_t)((r * 72 + c) * 2);
}
// A-fragment (m16k16) from [k][m] storage via trans-ldmatrix, pitch P
__device__ __forceinline__ uint32_t at_addr(uint32_t base, int m0, int k0, int lane, int P) {
    int t = lane >> 3;
    int m = m0 + ((t & 1) << 3);
    int k = k0 + ((t >> 1) << 3) + (lane & 7);
    return base + (uint32_t)((k * P + m) * 2);
}
// B-fragment x4 (two n8k16 tiles) from [n][k] row-major smem, pitch 72
__device__ __forceinline__ uint32_t b_addr(uint32_t base, int n0, int k0, int lane) {
    int r = n0 + (lane & 7) + ((lane >> 4) << 3), c = k0 + (((lane >> 3) & 1) << 3);
    return base + (uint32_t)((r * 72 + c) * 2);
}

// ---------------- scratch ----------------
__device__ __nv_bfloat16 d_xh[BB*C_*HW_], d_xl[BB*C_*HW_];
__device__ __nv_bfloat16 d_Wch[384*256],  d_Wcl[384*256];
__device__ float         d_bc[384];
__device__ __nv_bfloat16 d_Wfh[256*256],  d_Wfl[256*256];
__device__ __nv_bfloat16 d_Qh[BB*HW_*64],  d_Ql[BB*HW_*64];
__device__ __nv_bfloat16 d_Kh[BB*PHW_*64], d_Kl[BB*PHW_*64];
__device__ __nv_bfloat16 d_Vh[BB*C_*PHW_], d_Vl[BB*C_*PHW_];
__device__ __nv_bfloat16 d_Ph[(size_t)BB*HW_*PHW_], d_Pl[(size_t)BB*HW_*PHW_];
__device__ float         d_rinv[BB*HW_];
__device__ __nv_bfloat16 d_Yh[BB*HW_*C_],  d_Yl[BB*HW_*C_];

// ======================================================================
// xsplit + weight packing
// ======================================================================
__global__ __launch_bounds__(256) void xsplit_kernel(
    const float* __restrict__ x, __nv_bfloat16* __restrict__ xh, __nv_bfloat16* __restrict__ xl)
{
    size_t i = ((size_t)blockIdx.x * 256 + threadIdx.x) * 4;
    float4 v = *(const float4*)(x + i);
    uint32_t h0, l0, h1, l1;
    split2(v.x, v.y, h0, l0);
    split2(v.z, v.w, h1, l1);
    *(uint2*)(xh + i) = make_uint2(h0, h1);
    *(uint2*)(xl + i) = make_uint2(l0, l1);
}

__global__ void wpack_conv_kernel(
    const float* __restrict__ g_w, const float* __restrict__ g_b,
    const float* __restrict__ th_w, const float* __restrict__ th_b,
    const float* __restrict__ ph_w, const float* __restrict__ ph_b,
    __nv_bfloat16* __restrict__ Wh, __nv_bfloat16* __restrict__ Wl, float* __restrict__ bc)
{
    int oc = blockIdx.x, k = threadIdx.x;
    float v;
    if (oc < 256)       v = g_w[oc * 256 + k];
    else if (oc < 320)  v = (k < 64) ? th_w[(oc - 256) * 64 + k] : 0.f;
    else                v = (k >= 64) ? ph_w[(oc - 320) * 192 + (k - 64)] : 0.f;
    __nv_bfloat16 h, l; split_bf16(v, h, l);
    Wh[oc * 256 + k] = h; Wl[oc * 256 + k] = l;
    if (k == 0)
        bc[oc] = (oc < 256) ? g_b[oc] : (oc < 320) ? th_b[oc - 256] : ph_b[oc - 320];
}

__global__ void wpack_final_kernel(const float* __restrict__ w,
    __nv_bfloat16* __restrict__ Wh, __nv_bfloat16* __restrict__ Wl)
{
    int i = blockIdx.x * 256 + threadIdx.x;
    __nv_bfloat16 h, l; split_bf16(w[i], h, l);
    Wh[i] = h; Wl[i] = l;
}

// ======================================================================
// conv_mma: grid (3, 32, 8), block 512 (4x4 warps, 32x32 tiles); 2-stage.
// stage s @ s*71680: Xh[64][136] Xl(+17408) Wh[128][72](+34816) Wl(+53248)
// ======================================================================
static constexpr int CONV_STG = 71680;
static constexpr int CONV_SMEM = 2 * CONV_STG;

__global__ __launch_bounds__(512) void conv_mma_kernel(
    const __nv_bfloat16* __restrict__ xh, const __nv_bfloat16* __restrict__ xl,
    const __nv_bfloat16* __restrict__ Wh, const __nv_bfloat16* __restrict__ Wl,
    const float* __restrict__ bc,
    __nv_bfloat16* __restrict__ Vh, __nv_bfloat16* __restrict__ Vl,
    __nv_bfloat16* __restrict__ Qh, __nv_bfloat16* __restrict__ Ql,
    __nv_bfloat16* __restrict__ Kh, __nv_bfloat16* __restrict__ Kl)
{
    extern __shared__ char smem[];
    const uint32_t sb = smem_to_u32(smem);
    float* sRes = (float*)smem;
    const int tid = threadIdx.x, lane = tid & 31, wid = tid >> 5;
    const int wm = wid & 3, wn = wid >> 2;      // 4 x 4 warps, tile 32x32
    const int b = blockIdx.z, pxt = blockIdx.y, oc0 = blockIdx.x * 128;

    auto prefetch = [&](int c) {
        uint32_t base = sb + (c & 1) * CONV_STG;
        const __nv_bfloat16* gxh = xh + ((size_t)b * C_ + c * 64) * HW_ + pxt * 128;
        const __nv_bfloat16* gxl = xl + ((size_t)b * C_ + c * 64) * HW_ + pxt * 128;
        for (int idx = tid; idx < 1024; idx += 512) {
            int r = idx >> 4, u = idx & 15;
            uint32_t so = (uint32_t)((r * 136 + u * 8) * 2);
            cp16(base + so,         gxh + (size_t)r * HW_ + u * 8);
            cp16(base + 17408 + so, gxl + (size_t)r * HW_ + u * 8);
        }
        const __nv_bfloat16* gwh = Wh + (size_t)oc0 * 256 + c * 64;
        const __nv_bfloat16* gwl = Wl + (size_t)oc0 * 256 + c * 64;
        for (int idx = tid; idx < 1024; idx += 512) {
            int r = idx >> 3, u = idx & 7;
            uint32_t so = (uint32_t)((r * 72 + u * 8) * 2);
            cp16(base + 34816 + so, gwh + (size_t)r * 256 + u * 8);
            cp16(base + 53248 + so, gwl + (size_t)r * 256 + u * 8);
        }
        CP_COMMIT();
    };

    float acc[2][4][4];
#pragma unroll
    for (int mt = 0; mt < 2; mt++)
#pragma unroll
        for (int nt = 0; nt < 4; nt++)
#pragma unroll
            for (int e = 0; e < 4; e++) acc[mt][nt][e] = 0.f;

    prefetch(0);
    for (int ck = 0; ck < 4; ck++) {
        if (ck + 1 < 4) { prefetch(ck + 1); CP_WAIT1(); } else CP_WAIT0();
        __syncthreads();
        uint32_t base = sb + (ck & 1) * CONV_STG;
#pragma unroll
        for (int ks = 0; ks < 4; ks++) {
            const int k0 = ks * 16;
            uint32_t ah[2][4], al[2][4], bh[2][4], bl[2][4];
            ldsm4t(ah[0], at_addr(base, wm * 32,      k0, lane, 136));
            ldsm4t(ah[1], at_addr(base, wm * 32 + 16, k0, lane, 136));
            ldsm4(bh[0], b_addr(base + 34816, wn * 32,      k0, lane));
            ldsm4(bh[1], b_addr(base + 34816, wn * 32 + 16, k0, lane));
            // pass 1: hi*hi (8 independent)
#pragma unroll
            for (int g = 0; g < 2; g++)
#pragma unroll
                for (int mt = 0; mt < 2; mt++) {
                    mma16816(acc[mt][g*2],   ah[mt], bh[g][0], bh[g][1]);
                    mma16816(acc[mt][g*2+1], ah[mt], bh[g][2], bh[g][3]);
                }
            ldsm4(bl[0], b_addr(base + 53248, wn * 32,      k0, lane));
            ldsm4(bl[1], b_addr(base + 53248, wn * 32 + 16, k0, lane));
            // pass 2: hi*lo
#pragma unroll
            for (int g = 0; g < 2; g++)
#pragma unroll
                for (int mt = 0; mt < 2; mt++) {
                    mma16816(acc[mt][g*2],   ah[mt], bl[g][0], bl[g][1]);
                    mma16816(acc[mt][g*2+1], ah[mt], bl[g][2], bl[g][3]);
                }
            ldsm4t(al[0], at_addr(base + 17408, wm * 32,      k0, lane, 136));
            ldsm4t(al[1], at_addr(base + 17408, wm * 32 + 16, k0, lane, 136));
            // pass 3: lo*hi
#pragma unroll
            for (int g = 0; g < 2; g++)
#pragma unroll
                for (int mt = 0; mt < 2; mt++) {
                    mma16816(acc[mt][g*2],   al[mt], bh[g][0], bh[g][1]);
                    mma16816(acc[mt][g*2+1], al[mt], bh[g][2], bh[g][3]);
                }
        }
        __syncthreads();
    }

#pragma unroll
    for (int mt = 0; mt < 2; mt++) {
        const int row = wm * 32 + mt * 16 + (lane >> 2);
#pragma unroll
        for (int nt = 0; nt < 4; nt++) {
            const int col = wn * 32 + nt * 8 + (lane & 3) * 2;
            sRes[row * 132 + col]       = acc[mt][nt][0];
            sRes[row * 132 + col + 1]   = acc[mt][nt][1];
            sRes[(row+8) * 132 + col]   = acc[mt][nt][2];
            sRes[(row+8) * 132 + col+1] = acc[mt][nt][3];
        }
    }
    __syncthreads();

    if (oc0 < 256) {
        for (int t = tid; t < 32 * 128; t += 512) {
            int pw = t >> 7, lo = t & 127, oc = oc0 + lo;
            float v = fmaxf(fmaxf(sRes[(2*pw)*132 + lo], sRes[(2*pw+1)*132 + lo]),
                            fmaxf(sRes[(64+2*pw)*132 + lo], sRes[(65+2*pw)*132 + lo]))
                      + bc[oc];
            __nv_bfloat16 h, l; split_bf16(v, h, l);
            size_t oidx = ((size_t)b * C_ + oc) * PHW_ + pxt * 32 + pw;
            Vh[oidx] = h; Vl[oidx] = l;
        }
    } else {
        for (int t = tid; t < 128 * 64; t += 512) {
            int p = t >> 6, o = t & 63;
            float v = sRes[p * 132 + o] + bc[256 + o];
            __nv_bfloat16 h, l; split_bf16(v, h, l);
            size_t oidx = ((size_t)b * HW_ + pxt * 128 + p) * 64 + o;
            Qh[oidx] = h; Ql[oidx] = l;
        }
        for (int t = tid; t < 32 * 64; t += 512) {
            int pw = t >> 6, o = t & 63, lo = 64 + o;
            float v = fmaxf(fmaxf(sRes[(2*pw)*132 + lo], sRes[(2*pw+1)*132 + lo]),
                            fmaxf(sRes[(64+2*pw)*132 + lo], sRes[(65+2*pw)*132 + lo]))
                      + bc[320 + o];
            __nv_bfloat16 h, l; split_bf16(v, h, l);
            size_t oidx = ((size_t)b * PHW_ + pxt * 32 + pw) * 64 + o;
            Kh[oidx] = h; Kl[oidx] = l;
        }
    }
}

// ======================================================================
// qk_mma: S = Q K^T + fused exp/rowsum. grid (32, 8), block 256, 2 CTAs/SM.
// smem: Qh@0 Ql@18432; K stage s @ 36864 + s*36864 (hi@0, lo@18432); rs@110592
// ======================================================================
static constexpr int QK_SMEM = 110592 + 1024;

__global__ __launch_bounds__(256, 2) void qk_mma_kernel(
    const __nv_bfloat16* __restrict__ Qh, const __nv_bfloat16* __restrict__ Ql,
    const __nv_bfloat16* __restrict__ Kh, const __nv_bfloat16* __restrict__ Kl,
    __nv_bfloat16* __restrict__ Ph, __nv_bfloat16* __restrict__ Pl,
    float* __restrict__ rinv)
{
    extern __shared__ char smem[];
    const uint32_t sb = smem_to_u32(smem);
    __nv_bfloat16* sQ = (__nv_bfloat16*)smem;
    float* rs = (float*)(smem + 110592);
    const int tid = threadIdx.x, lane = tid & 31, wid = tid >> 5;
    const int wm = wid & 3, wn = wid >> 2;
    const int b = blockIdx.y, n0 = blockIdx.x * 128;

    auto prefetch = [&](int c) {
        uint32_t base = sb + 36864 + (c & 1) * 36864;
        const __nv_bfloat16* gkh = Kh + ((size_t)b * PHW_ + c * 128) * 64;
        const __nv_bfloat16* gkl = Kl + ((size_t)b * PHW_ + c * 128) * 64;
        for (int idx = tid; idx < 1024; idx += 256) {
            int r = idx >> 3, u = idx & 7;
            uint32_t so = (uint32_t)((r * 72 + u * 8) * 2);
            cp16(base + so,         gkh + r * 64 + u * 8);
            cp16(base + 18432 + so, gkl + r * 64 + u * 8);
        }
        CP_COMMIT();
    };

    prefetch(0);
    {
        const __nv_bfloat16* gqh = Qh + ((size_t)b * HW_ + n0) * 64;
        const __nv_bfloat16* gql = Ql + ((size_t)b * HW_ + n0) * 64;
        for (int idx = tid; idx < 1024; idx += 256) {
            int r = idx >> 3, u = idx & 7;
            *(uint4*)(sQ + r * 72 + u * 8)        = *(const uint4*)(gqh + r * 64 + u * 8);
            *(uint4*)(sQ + 9216 + r * 72 + u * 8) = *(const uint4*)(gql + r * 64 + u * 8);
        }
    }

    float rsum[2][2] = {{0.f, 0.f}, {0.f, 0.f}};

    for (int ck = 0; ck < 8; ck++) {
        const int m0 = ck * 128;
        if (ck + 1 < 8) { prefetch(ck + 1); CP_WAIT1(); } else CP_WAIT0();
        __syncthreads();
        uint32_t kb = sb + 36864 + (ck & 1) * 36864;

        float acc[2][8][4];
#pragma unroll
        for (int mt = 0; mt < 2; mt++)
#pragma unroll
            for (int nt = 0; nt < 8; nt++)
#pragma unroll
                for (int e = 0; e < 4; e++) acc[mt][nt][e] = 0.f;

#pragma unroll
        for (int ks = 0; ks < 4; ks++) {
            const int k0 = ks * 16;
            uint32_t ah[2][4], al[2][4];
            ldsm4(ah[0], a_addr(sb,         wm * 32,      k0, lane));
            ldsm4(ah[1], a_addr(sb,         wm * 32 + 16, k0, lane));
            ldsm4(al[0], a_addr(sb + 18432, wm * 32,      k0, lane));
            ldsm4(al[1], a_addr(sb + 18432, wm * 32 + 16, k0, lane));
#pragma unroll
            for (int g = 0; g < 4; g++) {
                uint32_t bh[4], bl[4];
                ldsm4(bh, b_addr(kb,         wn * 64 + g * 16, k0, lane));
                ldsm4(bl, b_addr(kb + 18432, wn * 64 + g * 16, k0, lane));
                // pass 1: hi*hi (4 indep), pass 2: hi*lo, pass 3: lo*hi
#pragma unroll
                for (int mt = 0; mt < 2; mt++) {
                    mma16816(acc[mt][g*2],   ah[mt], bh[0], bh[1]);
                    mma16816(acc[mt][g*2+1], ah[mt], bh[2], bh[3]);
                }
#pragma unroll
                for (int mt = 0; mt < 2; mt++) {
                    mma16816(acc[mt][g*2],   ah[mt], bl[0], bl[1]);
                    mma16816(acc[mt][g*2+1], ah[mt], bl[2], bl[3]);
                }
#pragma unroll
                for (int mt = 0; mt < 2; mt++) {
                    mma16816(acc[mt][g*2],   al[mt], bh[0], bh[1]);
                    mma16816(acc[mt][g*2+1], al[mt], bh[2], bh[3]);
                }
            }
        }

#pragma unroll
        for (int mt = 0; mt < 2; mt++) {
            const int row = n0 + wm * 32 + mt * 16 + (lane >> 2);
#pragma unroll
            for (int nt = 0; nt < 8; nt++) {
                float e0 = __expf(acc[mt][nt][0]);
                float e1 = __expf(acc[mt][nt][1]);
                float e2 = __expf(acc[mt][nt][2]);
                float e3 = __expf(acc[mt][nt][3]);
                rsum[mt][0] += e0 + e1;
                rsum[mt][1] += e2 + e3;
                const int col = m0 + wn * 64 + nt * 8 + (lane & 3) * 2;
                uint32_t hh, ll;
                split2(e0, e1, hh, ll);
                *(uint32_t*)&Ph[((size_t)b * HW_ + row) * PHW_ + col] = hh;
                *(uint32_t*)&Pl[((size_t)b * HW_ + row) * PHW_ + col] = ll;
                split2(e2, e3, hh, ll);
                *(uint32_t*)&Ph[((size_t)b * HW_ + row + 8) * PHW_ + col] = hh;
                *(uint32_t*)&Pl[((size_t)b * HW_ + row + 8) * PHW_ + col] = ll;
            }
        }
        __syncthreads();
    }

#pragma unroll
    for (int mt = 0; mt < 2; mt++)
#pragma unroll
        for (int hh = 0; hh < 2; hh++) {
            float s = rsum[mt][hh];
            s += __shfl_xor_sync(0xffffffffu, s, 1);
            s += __shfl_xor_sync(0xffffffffu, s, 2);
            if ((lane & 3) == 0)
                rs[wn * 128 + wm * 32 + mt * 16 + hh * 8 + (lane >> 2)] = s;
        }
    __syncthreads();
    if (tid < 128)
        rinv[(size_t)b * HW_ + n0 + tid] = 1.f / (rs[tid] + rs[128 + tid]);
}

// ======================================================================
// pv_mma: Y = exp(S) @ V * rinv. grid (32, 8), block 512; 2-stage.
// stage s @ s*110592: Ah[128][72] Al(+18432) Bh[256][72](+36864) Bl(+73728)
// Pass-reordered: all-g hi*hi, all-g hi*lo, all-g lo*hi (16 indep each).
// ======================================================================
static constexpr int PV_STG = 110592;
static constexpr int PV_SMEM = 2 * PV_STG;

__global__ __launch_bounds__(512) void pv_mma_kernel(
    const __nv_bfloat16* __restrict__ Ph, const __nv_bfloat16* __restrict__ Pl,
    const __nv_bfloat16* __restrict__ Vh, const __nv_bfloat16* __restrict__ Vl,
    const float* __restrict__ rinv,
    __nv_bfloat16* __restrict__ Yh, __nv_bfloat16* __restrict__ Yl)
{
    extern __shared__ char smem[];
    const uint32_t sb = smem_to_u32(smem);
    const int tid = threadIdx.x, lane = tid & 31, wid = tid >> 5;
    const int wm = wid & 3, wn = wid >> 2;
    const int b = blockIdx.y, n0 = blockIdx.x * 128;

    auto prefetch = [&](int c) {
        uint32_t base = sb + (c & 1) * PV_STG;
        const __nv_bfloat16* gph = Ph + ((size_t)b * HW_ + n0) * PHW_ + c * 64;
        const __nv_bfloat16* gpl = Pl + ((size_t)b * HW_ + n0) * PHW_ + c * 64;
        for (int idx = tid; idx < 1024; idx += 512) {
            int r = idx >> 3, u = idx & 7;
            uint32_t so = (uint32_t)((r * 72 + u * 8) * 2);
            cp16(base + so,         gph + (size_t)r * PHW_ + u * 8);
            cp16(base + 18432 + so, gpl + (size_t)r * PHW_ + u * 8);
        }
        const __nv_bfloat16* gvh = Vh + (size_t)b * C_ * PHW_ + c * 64;
        const __nv_bfloat16* gvl = Vl + (size_t)b * C_ * PHW_ + c * 64;
        for (int idx = tid; idx < 2048; idx += 512) {
            int r = idx >> 3, u = idx & 7;
            uint32_t so = (uint32_t)((r * 72 + u * 8) * 2);
            cp16(base + 36864 + so, gvh + (size_t)r * PHW_ + u * 8);
            cp16(base + 73728 + so, gvl + (size_t)r * PHW_ + u * 8);
        }
        CP_COMMIT();
    };

    float acc[2][8][4];
#pragma unroll
    for (int mt = 0; mt < 2; mt++)
#pragma unroll
        for (int nt = 0; nt < 8; nt++)
#pragma unroll
            for (int e = 0; e < 4; e++) acc[mt][nt][e] = 0.f;

    prefetch(0);
    for (int ck = 0; ck < 16; ck++) {
        if (ck + 1 < 16) { prefetch(ck + 1); CP_WAIT1(); } else CP_WAIT0();
        __syncthreads();
        uint32_t base = sb + (ck & 1) * PV_STG;
#pragma unroll
        for (int ks = 0; ks < 4; ks++) {
            const int k0 = ks * 16;
            uint32_t ah[2][4], al[2][4], bh[4][4], bl[4][4];
            ldsm4(ah[0], a_addr(base, wm * 32,      k0, lane));
            ldsm4(ah[1], a_addr(base, wm * 32 + 16, k0, lane));
#pragma unroll
            for (int g = 0; g < 4; g++)
                ldsm4(bh[g], b_addr(base + 36864, wn * 64 + g * 16, k0, lane));
            // pass 1: hi*hi (16 indep)
#pragma unroll
            for (int g = 0; g < 4; g++)
#pragma unroll
                for (int mt = 0; mt < 2; mt++) {
                    mma16816(acc[mt][g*2],   ah[mt], bh[g][0], bh[g][1]);
                    mma16816(acc[mt][g*2+1], ah[mt], bh[g][2], bh[g][3]);
                }
#pragma unroll
            for (int g = 0; g < 4; g++)
                ldsm4(bl[g], b_addr(base + 73728, wn * 64 + g * 16, k0, lane));
            // pass 2: hi*lo (16 indep)
#pragma unroll
            for (int g = 0; g < 4; g++)
#pragma unroll
                for (int mt = 0; mt < 2; mt++) {
                    mma16816(acc[mt][g*2],   ah[mt], bl[g][0], bl[g][1]);
                    mma16816(acc[mt][g*2+1], ah[mt], bl[g][2], bl[g][3]);
                }
            ldsm4(al[0], a_addr(base + 18432, wm * 32,      k0, lane));
            ldsm4(al[1], a_addr(base + 18432, wm * 32 + 16, k0, lane));
            // pass 3: lo*hi (16 indep)
#pragma unroll
            for (int g = 0; g < 4; g++)
#pragma unroll
                for (int mt = 0; mt < 2; mt++) {
                    mma16816(acc[mt][g*2],   al[mt], bh[g][0], bh[g][1]);
                    mma16816(acc[mt][g*2+1], al[mt], bh[g][2], bh[g][3]);
                }
        }
        __syncthreads();
    }

#pragma unroll
    for (int mt = 0; mt < 2; mt++) {
        const int r0 = n0 + wm * 32 + mt * 16 + (lane >> 2);
        const float i0 = rinv[(size_t)b * HW_ + r0];
        const float i1 = rinv[(size_t)b * HW_ + r0 + 8];
#pragma unroll
        for (int nt = 0; nt < 8; nt++) {
            const int col = wn * 64 + nt * 8 + (lane & 3) * 2;
            uint32_t hh, ll;
            split2(acc[mt][nt][0] * i0, acc[mt][nt][1] * i0, hh, ll);
            *(uint32_t*)&Yh[((size_t)b * HW_ + r0) * C_ + col] = hh;
            *(uint32_t*)&Yl[((size_t)b * HW_ + r0) * C_ + col] = ll;
            split2(acc[mt][nt][2] * i1, acc[mt][nt][3] * i1, hh, ll);
            *(uint32_t*)&Yh[((size_t)b * HW_ + r0 + 8) * C_ + col] = hh;
            *(uint32_t*)&Yl[((size_t)b * HW_ + r0 + 8) * C_ + col] = ll;
        }
    }
}

// ======================================================================
// final_mma: out = BN(Y @ W^T + Wb) + x. grid (2, 32, 8), block 512; 2-stage.
// stage s @ s*73728: Ah[128][72] Al(+18432) Bh[128][72](+36864) Bl(+55296)
// ======================================================================
static constexpr int FIN_STG = 73728;
static constexpr int FIN_SMEM = 2 * FIN_STG;

__global__ __launch_bounds__(512) void final_mma_kernel(
    const __nv_bfloat16* __restrict__ Yh, const __nv_bfloat16* __restrict__ Yl,
    const __nv_bfloat16* __restrict__ Wh, const __nv_bfloat16* __restrict__ Wl,
    const float* __restrict__ Wb,
    const float* __restrict__ gamma, const float* __restrict__ beta,
    const float* __restrict__ mean, const float* __restrict__ var,
    const float* __restrict__ x, float* __restrict__ out)
{
    extern __shared__ char smem[];
    const uint32_t sb = smem_to_u32(smem);
    float* sRes = (float*)smem;
    const int tid = threadIdx.x, lane = tid & 31, wid = tid >> 5;
    const int wm = wid & 3, wn = wid >> 2;      // 4 x 4, tile 32x32
    const int b = blockIdx.z, pxt = blockIdx.y, oc0 = blockIdx.x * 128;

    auto prefetch = [&](int c) {
        uint32_t base = sb + (c & 1) * FIN_STG;
        const __nv_bfloat16* gah = Yh + ((size_t)b * HW_ + pxt * 128) * C_ + c * 64;
        const __nv_bfloat16* gal = Yl + ((size_t)b * HW_ + pxt * 128) * C_ + c * 64;
        for (int idx = tid; idx < 1024; idx += 512) {
            int r = idx >> 3, u = idx & 7;
            uint32_t so = (uint32_t)((r * 72 + u * 8) * 2);
            cp16(base + so,         gah + (size_t)r * C_ + u * 8);
            cp16(base + 18432 + so, gal + (size_t)r * C_ + u * 8);
        }
        const __nv_bfloat16* gbh = Wh + (size_t)oc0 * 256 + c * 64;
        const __nv_bfloat16* gbl = Wl + (size_t)oc0 * 256 + c * 64;
        for (int idx = tid; idx < 1024; idx += 512) {
            int r = idx >> 3, u = idx & 7;
            uint32_t so = (uint32_t)((r * 72 + u * 8) * 2);
            cp16(base + 36864 + so, gbh + (size_t)r * 256 + u * 8);
            cp16(base + 55296 + so, gbl + (size_t)r * 256 + u * 8);
        }
        CP_COMMIT();
    };

    float acc[2][4][4];
#pragma unroll
    for (int mt = 0; mt < 2; mt++)
#pragma unroll
        for (int nt = 0; nt < 4; nt++)
#pragma unroll
            for (int e = 0; e < 4; e++) acc[mt][nt][e] = 0.f;

    prefetch(0);
    for (int ck = 0; ck < 4; ck++) {
        if (ck + 1 < 4) { prefetch(ck + 1); CP_WAIT1(); } else CP_WAIT0();
        __syncthreads();
        uint32_t base = sb + (ck & 1) * FIN_STG;
#pragma unroll
        for (int ks = 0; ks < 4; ks++) {
            const int k0 = ks * 16;
            uint32_t ah[2][4], al[2][4], bh[2][4], bl[2][4];
            ldsm4(ah[0], a_addr(base, wm * 32,      k0, lane));
            ldsm4(ah[1], a_addr(base, wm * 32 + 16, k0, lane));
            ldsm4(bh[0], b_addr(base + 36864, wn * 32,      k0, lane));
            ldsm4(bh[1], b_addr(base + 36864, wn * 32 + 16, k0, lane));
#pragma unroll
            for (int g = 0; g < 2; g++)
#pragma unroll
                for (int mt = 0; mt < 2; mt++) {
                    mma16816(acc[mt][g*2],   ah[mt], bh[g][0], bh[g][1]);
                    mma16816(acc[mt][g*2+1], ah[mt], bh[g][2], bh[g][3]);
                }
            ldsm4(bl[0], b_addr(base + 55296, wn * 32,      k0, lane));
            ldsm4(bl[1], b_addr(base + 55296, wn * 32 + 16, k0, lane));
#pragma unroll
            for (int g = 0; g < 2; g++)
#pragma unroll
                for (int mt = 0; mt < 2; mt++) {
                    mma16816(acc[mt][g*2],   ah[mt], bl[g][0], bl[g][1]);
                    mma16816(acc[mt][g*2+1], ah[mt], bl[g][2], bl[g][3]);
                }
            ldsm4(al[0], a_addr(base + 18432, wm * 32,      k0, lane));
            ldsm4(al[1], a_addr(base + 18432, wm * 32 + 16, k0, lane));
#pragma unroll
            for (int g = 0; g < 2; g++)
#pragma unroll
                for (int mt = 0; mt < 2; mt++) {
                    mma16816(acc[mt][g*2],   al[mt], bh[g][0], bh[g][1]);
                    mma16816(acc[mt][g*2+1], al[mt], bh[g][2], bh[g][3]);
                }
        }
        __syncthreads();
    }

#pragma unroll
    for (int mt = 0; mt < 2; mt++) {
        const int row = wm * 32 + mt * 16 + (lane >> 2);
#pragma unroll
        for (int nt = 0; nt < 4; nt++) {
            const int col = wn * 32 + nt * 8 + (lane & 3) * 2;
            sRes[row * 132 + col]       = acc[mt][nt][0];
            sRes[row * 132 + col + 1]   = acc[mt][nt][1];
            sRes[(row+8) * 132 + col]   = acc[mt][nt][2];
            sRes[(row+8) * 132 + col+1] = acc[mt][nt][3];
        }
    }
    __syncthreads();

    for (int t = tid; t < 128 * 128; t += 512) {
        int o = t >> 7, p = t & 127;
        int oc = oc0 + o;
        float scale = gamma[oc] * rsqrtf(var[oc] + EPS_);
        size_t gidx = ((size_t)b * C_ + oc) * HW_ + pxt * 128 + p;
        out[gidx] = (sRes[p * 132 + o] + Wb[oc] - mean[oc]) * scale + beta[oc] + x[gidx];
    }
}

// ======================================================================
extern "C" void kernel_launch(void* const* d_in, const int* in_sizes, int n_in,
                              void* d_out, int out_size)
{
    const float* x       = (const float*)d_in[0];
    const float* g_w     = (const float*)d_in[1];
    const float* g_b     = (const float*)d_in[2];
    const float* theta_w = (const float*)d_in[3];
    const float* theta_b = (const float*)d_in[4];
    const float* phi_w   = (const float*)d_in[5];
    const float* phi_b   = (const float*)d_in[6];
    const float* W_w     = (const float*)d_in[7];
    const float* W_b     = (const float*)d_in[8];
    const float* bn_g    = (const float*)d_in[9];
    const float* bn_b    = (const float*)d_in[10];
    const float* bn_m    = (const float*)d_in[11];
    const float* bn_v    = (const float*)d_in[12];
    float* out = (float*)d_out;

    __nv_bfloat16 *xh, *xl, *Wch, *Wcl, *Wfh, *Wfl;
    __nv_bfloat16 *Qh, *Ql, *Kh, *Kl, *Vh, *Vl, *Ph, *Pl, *Yh, *Yl;
    float *rv, *bc;
    cudaGetSymbolAddress((void**)&xh,  d_xh);
    cudaGetSymbolAddress((void**)&xl,  d_xl);
    cudaGetSymbolAddress((void**)&Wch, d_Wch);
    cudaGetSymbolAddress((void**)&Wcl, d_Wcl);
    cudaGetSymbolAddress((void**)&bc,  d_bc);
    cudaGetSymbolAddress((void**)&Wfh, d_Wfh);
    cudaGetSymbolAddress((void**)&Wfl, d_Wfl);
    cudaGetSymbolAddress((void**)&Qh,  d_Qh);
    cudaGetSymbolAddress((void**)&Ql,  d_Ql);
    cudaGetSymbolAddress((void**)&Kh,  d_Kh);
    cudaGetSymbolAddress((void**)&Kl,  d_Kl);
    cudaGetSymbolAddress((void**)&Vh,  d_Vh);
    cudaGetSymbolAddress((void**)&Vl,  d_Vl);
    cudaGetSymbolAddress((void**)&Ph,  d_Ph);
    cudaGetSymbolAddress((void**)&Pl,  d_Pl);
    cudaGetSymbolAddress((void**)&rv,  d_rinv);
    cudaGetSymbolAddress((void**)&Yh,  d_Yh);
    cudaGetSymbolAddress((void**)&Yl,  d_Yl);

    cudaFuncSetAttribute(conv_mma_kernel,  cudaFuncAttributeMaxDynamicSharedMemorySize, CONV_SMEM);
    cudaFuncSetAttribute(qk_mma_kernel,    cudaFuncAttributeMaxDynamicSharedMemorySize, QK_SMEM);
    cudaFuncSetAttribute(pv_mma_kernel,    cudaFuncAttributeMaxDynamicSharedMemorySize, PV_SMEM);
    cudaFuncSetAttribute(final_mma_kernel, cudaFuncAttributeMaxDynamicSharedMemorySize, FIN_SMEM);

    xsplit_kernel<<<BB * C_ * HW_ / 1024, 256>>>(x, xh, xl);
    wpack_conv_kernel<<<384, 256>>>(g_w, g_b, theta_w, theta_b, phi_w, phi_b, Wch, Wcl, bc);
    wpack_final_kernel<<<256, 256>>>(W_w, Wfh, Wfl);
    conv_mma_kernel<<<dim3(3, 32, BB), 512, CONV_SMEM>>>(xh, xl, Wch, Wcl, bc,
                                                         Vh, Vl, Qh, Ql, Kh, Kl);
    qk_mma_kernel<<<dim3(32, BB), 256, QK_SMEM>>>(Qh, Ql, Kh, Kl, Ph, Pl, rv);
    pv_mma_kernel<<<dim3(32, BB), 512, PV_SMEM>>>(Ph, Pl, Vh, Vl, rv, Yh, Yl);
    final_mma_kernel<<<dim3(2, 32, BB), 512, FIN_SMEM>>>(Yh, Yl, Wfh, Wfl, W_b,
                                                         bn_g, bn_b, bn_m, bn_v, x, out);
}